// round 8
// baseline (speedup 1.0000x reference)
#include <cuda_runtime.h>
#include <cuda_bf16.h>
#include <cstdint>
#include <cstring>

// Problem constants
#define B_   2
#define C_   64
#define H_   192
#define W_   192
#define HW_  (H_*W_)          // 36864
#define KK_  9
#define HP_  194
#define WP_  194
#define HPWP_ (HP_*WP_)       // 37636
#define CI_  65               // C+1
#define OC_  18               // 2*KK
#define KTOT_ 640             // offconv GEMM K (10 chunks of 64)

// Scratch (device globals)
__device__ float    g_xp  [B_*HPWP_*C_];     // padded x, NHWC  (~19.3 MB)
__device__ float    g_off [B_*OC_*HW_];      // offsets (~5.3 MB)
__device__ uint16_t g_wtbh[KK_*C_*C_];       // fused weight hi bf16, [kk][oc][c]
__device__ uint16_t g_wtbl[KK_*C_*C_];       // fused weight lo bf16
__device__ uint16_t g_wobh[32*KTOT_];        // offconv weight hi bf16, [oc32][k640]
__device__ uint16_t g_wobl[32*KTOT_];        // offconv weight lo bf16

// ---------------------------------------------------------------------------
// helpers
// ---------------------------------------------------------------------------
__device__ __forceinline__ uint32_t cvt_bf16x2(float hi, float lo) {
    uint32_t r;
    asm("cvt.rn.satfinite.bf16x2.f32 %0, %1, %2;" : "=r"(r) : "f"(hi), "f"(lo));
    return r;
}

__device__ __forceinline__ void mma16816(float& d0, float& d1, float& d2, float& d3,
                                         uint32_t a0, uint32_t a1, uint32_t a2, uint32_t a3,
                                         uint32_t b0, uint32_t b1) {
    asm volatile("mma.sync.aligned.m16n8k16.row.col.f32.bf16.bf16.f32 "
                 "{%0,%1,%2,%3},{%4,%5,%6,%7},{%8,%9},{%0,%1,%2,%3};"
                 : "+f"(d0), "+f"(d1), "+f"(d2), "+f"(d3)
                 : "r"(a0), "r"(a1), "r"(a2), "r"(a3), "r"(b0), "r"(b1));
}

__device__ __forceinline__ void bf16_split(float v, uint16_t& h, uint16_t& l) {
    __nv_bfloat16 hb = __float2bfloat16(v);
    float hf = __bfloat162float(hb);
    __nv_bfloat16 lb = __float2bfloat16(v - hf);
    memcpy(&h, &hb, 2); memcpy(&l, &lb, 2);
}

// ---------------------------------------------------------------------------
// Kernel 1: merged prep — job y=0: pad border of g_xp; y=1: fused weight
// bf16 hi/lo; y=2: offconv weight bf16 hi/lo (padded to [32][640]).
// ---------------------------------------------------------------------------
#define NBORD_ (2*WP_ + 2*(HP_-2))   // 772
__global__ void prep_kernel(const float* __restrict__ w,
                            const float* __restrict__ w_off) {
    int i = blockIdx.x * blockDim.x + threadIdx.x;
    int job = blockIdx.y;
    if (job == 0) {
        if (i >= B_ * NBORD_ * 16) return;
        int b   = i / (NBORD_ * 16);
        int r   = i % (NBORD_ * 16);
        int pix = r >> 4;
        int cq  = r & 15;
        int ph, pw;
        if (pix < WP_)            { ph = 0;        pw = pix; }
        else if (pix < 2*WP_)     { ph = HP_ - 1;  pw = pix - WP_; }
        else if (pix < 2*WP_ + (HP_-2)) { ph = pix - 2*WP_ + 1;  pw = 0; }
        else                      { ph = pix - (2*WP_ + (HP_-2)) + 1; pw = WP_ - 1; }
        reinterpret_cast<float4*>(g_xp + ((size_t)b * HPWP_ + ph * WP_ + pw) * C_)[cq] =
            make_float4(0.f, 0.f, 0.f, 0.f);
    } else if (job == 1) {
        if (i >= KK_*C_*C_) return;
        int kk = i / (C_*C_);
        int oc = (i >> 6) & 63;
        int c  = i & 63;
        float v = w[oc * 576 + c * KK_ + kk];
        uint16_t hb, lb; bf16_split(v, hb, lb);
        g_wtbh[(kk * C_ + oc) * C_ + c] = hb;
        g_wtbl[(kk * C_ + oc) * C_ + c] = lb;
    } else {
        if (i >= 32*KTOT_) return;
        int o = i / KTOT_, k = i % KTOT_;
        float v = 0.f;
        if (o < OC_) {
            if (k < 576) {            // k = c + 64*t
                int c = k & 63, t = k >> 6;
                v = w_off[(o * CI_ + c) * KK_ + t];
            } else if (k < 585) {     // depth taps
                int t = k - 576;
                v = w_off[(o * CI_ + 64) * KK_ + t];
            }
        }
        uint16_t hb, lb; bf16_split(v, hb, lb);
        g_wobh[i] = hb;
        g_wobl[i] = lb;
    }
}

// ---------------------------------------------------------------------------
// Kernel 2: NCHW -> padded NHWC transpose (interior)
// ---------------------------------------------------------------------------
__global__ __launch_bounds__(256) void nhwc_kernel(const float* __restrict__ x) {
    __shared__ float tile[C_][33];
    const int tid = threadIdx.x;
    const int b   = blockIdx.y;
    const int pix0 = blockIdx.x * 32;

    {
        int ty = tid >> 5, tx = tid & 31;
        #pragma unroll
        for (int c0 = 0; c0 < C_; c0 += 8)
            tile[c0 + ty][tx] = x[((size_t)b * C_ + c0 + ty) * HW_ + pix0 + tx];
    }
    __syncthreads();
    {
        int pi = tid >> 6, c = tid & 63;
        #pragma unroll
        for (int j = 0; j < 8; ++j) {
            int pix = pix0 + j * 4 + pi;
            int ph = pix / W_ + 1, pw = pix % W_ + 1;
            g_xp[((size_t)b * HPWP_ + ph * WP_ + pw) * C_ + c] = tile[c][j * 4 + pi];
        }
    }
}

// ---------------------------------------------------------------------------
// Kernel 3: offconv as mma.sync GEMM (3-term bf16 split).
// Block: 64 px (M) x 32 oc (N, 18 used), 128 threads / 4 warps
// (warp w owns px rows w*16..w*16+15, all 32 oc).
// K = 640: chunks ch=0..8 -> tap t=ch over 64 channels (k = ch*64 + c),
// ch=9 -> 9 depth taps (k=576+t), rest zero (B rows zeroed in prep).
// A tile [64 px][64 k] bf16 hi/lo, pitch 72, double buffered.
// Each 64-px tile lies in ONE image row (64 | 192) -> trivial edge handling.
// ---------------------------------------------------------------------------
__global__ __launch_bounds__(128) void offmma_kernel(
    const float* __restrict__ x, const float* __restrict__ depth,
    const float* __restrict__ bias)
{
    __shared__ __align__(16) uint16_t Ahi[2][64 * 72];   // 2 x 9216 B
    __shared__ __align__(16) uint16_t Alo[2][64 * 72];   // 2 x 9216 B

    const int tid  = threadIdx.x;
    const int wid  = tid >> 5;
    const int lane = tid & 31;
    const int b    = blockIdx.y;
    const int pix0 = blockIdx.x * 64;
    const int oh   = pix0 / W_;
    const int ow0  = pix0 % W_;

    // A-fill: thread handles k-column (tid>>1) for 32 px (half tid&1)
    const int col = tid >> 1;
    const int j0  = (tid & 1) * 32;

    auto gather = [&](int ch, int buf) {
        const float* plane;
        int dy, dx;
        if (ch < 9) {
            dy = ch / 3 - 1; dx = ch % 3 - 1;
            plane = x + ((size_t)b * C_ + col) * HW_;
        } else {
            if (col >= 9) return;           // B rows zero -> A garbage harmless
            dy = col / 3 - 1; dx = col % 3 - 1;
            plane = depth + (size_t)b * HW_;
        }
        const int ih = oh + dy;
        const bool rowv = ((unsigned)ih < (unsigned)H_);
        const float* rp = plane + ih * W_;
        #pragma unroll
        for (int g = 0; g < 4; ++g) {
            float v[8];
            #pragma unroll
            for (int e = 0; e < 8; ++e) {
                int iw = ow0 + dx + j0 + g * 8 + e;
                v[e] = (rowv && (unsigned)iw < (unsigned)W_) ? rp[iw] : 0.f;
            }
            #pragma unroll
            for (int e = 0; e < 8; e += 2) {
                float v0 = v[e], v1 = v[e + 1];
                uint32_t h = cvt_bf16x2(v1, v0);            // lo16 = v0
                float l0 = v0 - __uint_as_float(h << 16);
                float l1 = v1 - __uint_as_float(h & 0xFFFF0000u);
                uint32_t l = cvt_bf16x2(l1, l0);
                int a0 = (j0 + g * 8 + e) * 72 + col;
                Ahi[buf][a0]      = (uint16_t)h;
                Ahi[buf][a0 + 72] = (uint16_t)(h >> 16);
                Alo[buf][a0]      = (uint16_t)l;
                Alo[buf][a0 + 72] = (uint16_t)(l >> 16);
            }
        }
    };

    float acc[4][4];
    #pragma unroll
    for (int ni = 0; ni < 4; ++ni)
        #pragma unroll
        for (int r = 0; r < 4; ++r) acc[ni][r] = 0.f;

    const int arow0 = wid * 16 + (lane >> 2);
    const int akol  = (lane & 3) * 2;
    const int brow  = lane >> 2;

    gather(0, 0);
    __syncthreads();

    for (int ch = 0; ch < 10; ++ch) {
        const int buf = ch & 1;
        const uint16_t* wh = g_wobh + ch * 64;
        const uint16_t* wl = g_wobl + ch * 64;
        const int nki = (ch == 9) ? 1 : 4;     // depth chunk: only k 0..15 nonzero

        for (int ki = 0; ki < nki; ++ki) {
            const int k0 = ki * 16 + akol;
            const int r0 = arow0 * 72 + k0;
            uint32_t a0h = *reinterpret_cast<const uint32_t*>(&Ahi[buf][r0]);
            uint32_t a1h = *reinterpret_cast<const uint32_t*>(&Ahi[buf][r0 + 8 * 72]);
            uint32_t a2h = *reinterpret_cast<const uint32_t*>(&Ahi[buf][r0 + 8]);
            uint32_t a3h = *reinterpret_cast<const uint32_t*>(&Ahi[buf][r0 + 8 * 72 + 8]);
            uint32_t a0l = *reinterpret_cast<const uint32_t*>(&Alo[buf][r0]);
            uint32_t a1l = *reinterpret_cast<const uint32_t*>(&Alo[buf][r0 + 8 * 72]);
            uint32_t a2l = *reinterpret_cast<const uint32_t*>(&Alo[buf][r0 + 8]);
            uint32_t a3l = *reinterpret_cast<const uint32_t*>(&Alo[buf][r0 + 8 * 72 + 8]);
            #pragma unroll
            for (int ni = 0; ni < 4; ++ni) {
                int boff = (ni * 8 + brow) * KTOT_ + k0;
                uint32_t bh0 = *reinterpret_cast<const uint32_t*>(wh + boff);
                uint32_t bh1 = *reinterpret_cast<const uint32_t*>(wh + boff + 8);
                uint32_t bl0 = *reinterpret_cast<const uint32_t*>(wl + boff);
                uint32_t bl1 = *reinterpret_cast<const uint32_t*>(wl + boff + 8);
                float* d = acc[ni];
                mma16816(d[0], d[1], d[2], d[3], a0h, a1h, a2h, a3h, bh0, bh1);
                mma16816(d[0], d[1], d[2], d[3], a0l, a1l, a2l, a3l, bh0, bh1);
                mma16816(d[0], d[1], d[2], d[3], a0h, a1h, a2h, a3h, bl0, bl1);
            }
        }
        if (ch + 1 < 10) gather(ch + 1, buf ^ 1);
        __syncthreads();
    }

    // epilogue: D [16px][32oc] per warp -> g_off[b][oc][px] (+bias), oc<18 only
    const int px = pix0 + wid * 16 + (lane >> 2);
    #pragma unroll
    for (int ni = 0; ni < 4; ++ni) {
        int oc = ni * 8 + (lane & 3) * 2;
        if (oc < OC_) {
            float b0 = bias[oc], b1 = bias[oc + 1];
            float* o0 = g_off + ((size_t)b * OC_ + oc) * HW_;
            float* o1 = g_off + ((size_t)b * OC_ + oc + 1) * HW_;
            o0[px]     = acc[ni][0] + b0;
            o1[px]     = acc[ni][1] + b1;
            o0[px + 8] = acc[ni][2] + b0;
            o1[px + 8] = acc[ni][3] + b1;
        }
    }
}

// ---------------------------------------------------------------------------
// Kernel 4: fused bilinear gather + mma.sync bf16 GEMM (unchanged from R6)
// ---------------------------------------------------------------------------
#define APITCH_ 72

struct __align__(8) TapA { float ax, ay; };

__global__ __launch_bounds__(128) void fused_mma_kernel(float* __restrict__ out)
{
    __shared__ __align__(16) uint16_t Ahi[2][64 * APITCH_];
    __shared__ __align__(16) uint16_t Alo[2][64 * APITCH_];
    __shared__ int  tap_idx[KK_][64];
    __shared__ TapA tap_a  [KK_][64];

    const int tid  = threadIdx.x;
    const int wid  = tid >> 5;
    const int lane = tid & 31;
    const int b    = blockIdx.y;
    const int pix0 = blockIdx.x * 64;

    const int pxg = wid & 1;
    const int ocg = wid >> 1;

    float acc[2][4][4];
    #pragma unroll
    for (int mi = 0; mi < 2; ++mi)
        #pragma unroll
        for (int ni = 0; ni < 4; ++ni)
            #pragma unroll
            for (int r = 0; r < 4; ++r) acc[mi][ni][r] = 0.f;

    const float* xb = g_xp + (size_t)b * HPWP_ * C_;
    const int cg = tid & 15;
    const int pb = tid >> 4;

    for (int e = tid; e < KK_ * 64; e += 128) {
        int kk = e >> 6;
        int p  = e & 63;
        int pix = pix0 + p;
        int oh = pix / W_, ow = pix % W_;
        float ox = g_off[((size_t)b * OC_ + kk) * HW_ + pix];
        float oy = g_off[((size_t)b * OC_ + KK_ + kk) * HW_ + pix];
        float cx = (float)(oh + kk / 3) + ox;
        float cy = (float)(ow + kk % 3) + oy;
        cx = fminf(fmaxf(cx, 0.f), (float)(HP_ - 1));
        cy = fminf(fmaxf(cy, 0.f), (float)(WP_ - 1));
        int tlx = (int)floorf(cx); tlx = min(max(tlx, 0), HP_ - 2);
        int tly = (int)floorf(cy); tly = min(max(tly, 0), WP_ - 2);
        tap_idx[kk][p] = tlx * WP_ + tly;
        tap_a[kk][p].ax = cx - (float)tlx;
        tap_a[kk][p].ay = cy - (float)tly;
    }
    __syncthreads();

    auto gather = [&](int kk, int buf) {
        #pragma unroll 2
        for (int i = 0; i < 8; ++i) {
            int p = pb + 8 * i;
            int idx = tap_idx[kk][p];
            TapA a = tap_a[kk][p];
            const float4* q = reinterpret_cast<const float4*>(xb + (size_t)idx * C_) + cg;
            float4 x00 = q[0];
            float4 x01 = q[16];
            float4 x10 = q[WP_ * 16];
            float4 x11 = q[(WP_ + 1) * 16];
            float4 v;
            {
                float r0, r1;
                r0 = fmaf(a.ay, x01.x - x00.x, x00.x);
                r1 = fmaf(a.ay, x11.x - x10.x, x10.x);
                v.x = fmaf(a.ax, r1 - r0, r0);
                r0 = fmaf(a.ay, x01.y - x00.y, x00.y);
                r1 = fmaf(a.ay, x11.y - x10.y, x10.y);
                v.y = fmaf(a.ax, r1 - r0, r0);
                r0 = fmaf(a.ay, x01.z - x00.z, x00.z);
                r1 = fmaf(a.ay, x11.z - x10.z, x10.z);
                v.z = fmaf(a.ax, r1 - r0, r0);
                r0 = fmaf(a.ay, x01.w - x00.w, x00.w);
                r1 = fmaf(a.ay, x11.w - x10.w, x10.w);
                v.w = fmaf(a.ax, r1 - r0, r0);
            }
            uint32_t h01 = cvt_bf16x2(v.y, v.x);
            uint32_t h23 = cvt_bf16x2(v.w, v.z);
            float l0 = v.x - __uint_as_float(h01 << 16);
            float l1 = v.y - __uint_as_float(h01 & 0xFFFF0000u);
            float l2 = v.z - __uint_as_float(h23 << 16);
            float l3 = v.w - __uint_as_float(h23 & 0xFFFF0000u);
            uint32_t q01 = cvt_bf16x2(l1, l0);
            uint32_t q23 = cvt_bf16x2(l3, l2);
            int eo = p * APITCH_ + cg * 4;
            *reinterpret_cast<uint2*>(&Ahi[buf][eo]) = make_uint2(h01, h23);
            *reinterpret_cast<uint2*>(&Alo[buf][eo]) = make_uint2(q01, q23);
        }
    };

    gather(0, 0);
    __syncthreads();

    const int arow = pxg * 32 + (lane >> 2);
    const int akol = (lane & 3) * 2;
    const int brow = ocg * 32 + (lane >> 2);

    for (int kk = 0; kk < KK_; ++kk) {
        const int buf = kk & 1;
        const uint16_t* wh = g_wtbh + kk * (C_*C_);
        const uint16_t* wl = g_wtbl + kk * (C_*C_);

        #pragma unroll
        for (int ki = 0; ki < 4; ++ki) {
            const int k0 = ki * 16 + akol;
            uint32_t ah[2][4], al[2][4];
            #pragma unroll
            for (int mi = 0; mi < 2; ++mi) {
                int r0 = (arow + mi * 16) * APITCH_ + k0;
                int r1 = r0 + 8 * APITCH_;
                ah[mi][0] = *reinterpret_cast<const uint32_t*>(&Ahi[buf][r0]);
                ah[mi][1] = *reinterpret_cast<const uint32_t*>(&Ahi[buf][r1]);
                ah[mi][2] = *reinterpret_cast<const uint32_t*>(&Ahi[buf][r0 + 8]);
                ah[mi][3] = *reinterpret_cast<const uint32_t*>(&Ahi[buf][r1 + 8]);
                al[mi][0] = *reinterpret_cast<const uint32_t*>(&Alo[buf][r0]);
                al[mi][1] = *reinterpret_cast<const uint32_t*>(&Alo[buf][r1]);
                al[mi][2] = *reinterpret_cast<const uint32_t*>(&Alo[buf][r0 + 8]);
                al[mi][3] = *reinterpret_cast<const uint32_t*>(&Alo[buf][r1 + 8]);
            }
            #pragma unroll
            for (int ni = 0; ni < 4; ++ni) {
                int boff = (brow + ni * 8) * C_ + k0;
                uint32_t bh0 = *reinterpret_cast<const uint32_t*>(wh + boff);
                uint32_t bh1 = *reinterpret_cast<const uint32_t*>(wh + boff + 8);
                uint32_t bl0 = *reinterpret_cast<const uint32_t*>(wl + boff);
                uint32_t bl1 = *reinterpret_cast<const uint32_t*>(wl + boff + 8);
                #pragma unroll
                for (int mi = 0; mi < 2; ++mi) {
                    float* d = acc[mi][ni];
                    mma16816(d[0], d[1], d[2], d[3],
                             ah[mi][0], ah[mi][1], ah[mi][2], ah[mi][3], bh0, bh1);
                    mma16816(d[0], d[1], d[2], d[3],
                             al[mi][0], al[mi][1], al[mi][2], al[mi][3], bh0, bh1);
                    mma16816(d[0], d[1], d[2], d[3],
                             ah[mi][0], ah[mi][1], ah[mi][2], ah[mi][3], bl0, bl1);
                }
            }
        }
        if (kk + 1 < KK_) gather(kk + 1, buf ^ 1);
        __syncthreads();
    }

    #pragma unroll
    for (int mi = 0; mi < 2; ++mi) {
        int px = pix0 + pxg * 32 + mi * 16 + (lane >> 2);
        #pragma unroll
        for (int ni = 0; ni < 4; ++ni) {
            int oc = ocg * 32 + ni * 8 + (lane & 3) * 2;
            float* o0 = out + ((size_t)b * C_ + oc) * HW_;
            float* o1 = out + ((size_t)b * C_ + oc + 1) * HW_;
            o0[px]     = acc[mi][ni][0];
            o1[px]     = acc[mi][ni][1];
            o0[px + 8] = acc[mi][ni][2];
            o1[px + 8] = acc[mi][ni][3];
        }
    }
}

// ---------------------------------------------------------------------------
// Launch
// ---------------------------------------------------------------------------
extern "C" void kernel_launch(void* const* d_in, const int* in_sizes, int n_in,
                              void* d_out, int out_size) {
    const float* x      = (const float*)d_in[0];
    const float* depth  = (const float*)d_in[1];
    const float* w_off  = (const float*)d_in[2];
    const float* bias   = (const float*)d_in[3];
    const float* weight = (const float*)d_in[4];
    float* out = (float*)d_out;

    {
        dim3 grid(144, 3);   // 144*256 = 36864 >= all three job sizes
        prep_kernel<<<grid, 256>>>(weight, w_off);
    }
    {
        dim3 grid(HW_ / 32, B_);
        nhwc_kernel<<<grid, 256>>>(x);
    }
    {
        dim3 grid(HW_ / 64, B_);
        offmma_kernel<<<grid, 128>>>(x, depth, bias);
    }
    {
        dim3 grid(HW_ / 64, B_);
        fused_mma_kernel<<<grid, 128>>>(out);
    }
}

// round 9
// speedup vs baseline: 2.1220x; 2.1220x over previous
#include <cuda_runtime.h>
#include <cuda_bf16.h>
#include <cstdint>
#include <cstring>

// Problem constants
#define B_   2
#define C_   64
#define H_   192
#define W_   192
#define HW_  (H_*W_)          // 36864
#define KK_  9
#define HP_  194
#define WP_  194
#define HPWP_ (HP_*WP_)       // 37636
#define CI_  65               // C+1
#define OC_  18               // 2*KK
#define OCH_ 9                // oc per offconv block

// Scratch (device globals)
__device__ float    g_xp  [B_*HPWP_*C_];     // padded x, NHWC  (~19.3 MB)
__device__ float    g_off [B_*OC_*HW_];      // offsets (~5.3 MB)
__device__ uint16_t g_wtbh[KK_*C_*C_];       // fused weight hi bf16, [kk][oc][c]
__device__ uint16_t g_wtbl[KK_*C_*C_];       // fused weight lo bf16

// ---------------------------------------------------------------------------
// helpers
// ---------------------------------------------------------------------------
__device__ __forceinline__ uint32_t cvt_bf16x2(float hi, float lo) {
    uint32_t r;
    asm("cvt.rn.satfinite.bf16x2.f32 %0, %1, %2;" : "=r"(r) : "f"(hi), "f"(lo));
    return r;
}

__device__ __forceinline__ void mma16816(float& d0, float& d1, float& d2, float& d3,
                                         uint32_t a0, uint32_t a1, uint32_t a2, uint32_t a3,
                                         uint32_t b0, uint32_t b1) {
    asm volatile("mma.sync.aligned.m16n8k16.row.col.f32.bf16.bf16.f32 "
                 "{%0,%1,%2,%3},{%4,%5,%6,%7},{%8,%9},{%0,%1,%2,%3};"
                 : "+f"(d0), "+f"(d1), "+f"(d2), "+f"(d3)
                 : "r"(a0), "r"(a1), "r"(a2), "r"(a3), "r"(b0), "r"(b1));
}

// ---------------------------------------------------------------------------
// Kernel 1: merged prep — job y=0: pad border of g_xp; y=1: fused weight hi/lo
// ---------------------------------------------------------------------------
#define NBORD_ (2*WP_ + 2*(HP_-2))   // 772
__global__ void prep_kernel(const float* __restrict__ w) {
    int i = blockIdx.x * blockDim.x + threadIdx.x;
    int job = blockIdx.y;
    if (job == 0) {
        if (i >= B_ * NBORD_ * 16) return;
        int b   = i / (NBORD_ * 16);
        int r   = i % (NBORD_ * 16);
        int pix = r >> 4;
        int cq  = r & 15;
        int ph, pw;
        if (pix < WP_)            { ph = 0;        pw = pix; }
        else if (pix < 2*WP_)     { ph = HP_ - 1;  pw = pix - WP_; }
        else if (pix < 2*WP_ + (HP_-2)) { ph = pix - 2*WP_ + 1;  pw = 0; }
        else                      { ph = pix - (2*WP_ + (HP_-2)) + 1; pw = WP_ - 1; }
        reinterpret_cast<float4*>(g_xp + ((size_t)b * HPWP_ + ph * WP_ + pw) * C_)[cq] =
            make_float4(0.f, 0.f, 0.f, 0.f);
    } else {
        if (i >= KK_*C_*C_) return;
        int kk = i / (C_*C_);
        int oc = (i >> 6) & 63;
        int c  = i & 63;
        float v = w[oc * 576 + c * KK_ + kk];
        __nv_bfloat16 h = __float2bfloat16(v);
        float hf = __bfloat162float(h);
        __nv_bfloat16 l = __float2bfloat16(v - hf);
        uint16_t hb, lb;
        memcpy(&hb, &h, 2); memcpy(&lb, &l, 2);
        g_wtbh[(kk * C_ + oc) * C_ + c] = hb;
        g_wtbl[(kk * C_ + oc) * C_ + c] = lb;
    }
}

// ---------------------------------------------------------------------------
// Kernel 2: NCHW -> padded NHWC transpose (interior)
// ---------------------------------------------------------------------------
__global__ __launch_bounds__(256) void nhwc_kernel(const float* __restrict__ x) {
    __shared__ float tile[C_][33];
    const int tid = threadIdx.x;
    const int b   = blockIdx.y;
    const int pix0 = blockIdx.x * 32;

    {
        int ty = tid >> 5, tx = tid & 31;
        #pragma unroll
        for (int c0 = 0; c0 < C_; c0 += 8)
            tile[c0 + ty][tx] = x[((size_t)b * C_ + c0 + ty) * HW_ + pix0 + tx];
    }
    __syncthreads();
    {
        int pi = tid >> 6, c = tid & 63;
        #pragma unroll
        for (int j = 0; j < 8; ++j) {
            int pix = pix0 + j * 4 + pi;
            int ph = pix / W_ + 1, pw = pix % W_ + 1;
            g_xp[((size_t)b * HPWP_ + ph * WP_ + pw) * C_ + c] = tile[c][j * 4 + pi];
        }
    }
}

// ---------------------------------------------------------------------------
// Kernel 3: offset-predicting conv (R6 proven version).
// 256 threads, 2 pixels/thread, 9 of 18 oc per block.
// smem weights as [c][tap][12] -> 2xLDS.128+LDS.32 per (c,tap).
// ---------------------------------------------------------------------------
#define WPITCH_ 12
__global__ __launch_bounds__(256) void offconv_kernel(
    const float* __restrict__ x, const float* __restrict__ depth,
    const float* __restrict__ w_off, const float* __restrict__ bias)
{
    __shared__ __align__(16) float w_s[CI_*KK_*WPITCH_];   // 28080 B
    const int tid = threadIdx.x;
    const int ocg = blockIdx.y;           // 0/1
    const int b   = blockIdx.z;
    const int ob  = ocg * OCH_;

    for (int i = tid; i < CI_*KK_*OCH_; i += 256) {
        int ct = i / OCH_, o = i % OCH_;
        w_s[ct * WPITCH_ + o] = w_off[(ob + o) * (CI_*KK_) + ct];
    }
    __syncthreads();

    const int p0 = blockIdx.x * 512 + tid;
    const int p1 = p0 + 256;

    int ti0[KK_], ti1[KK_];
    {
        int oh0 = p0 / W_, ow0 = p0 % W_;
        int oh1 = p1 / W_, ow1 = p1 % W_;
        #pragma unroll
        for (int t = 0; t < KK_; ++t) {
            int ky = t / 3 - 1, kx = t % 3 - 1;
            int ih0 = oh0 + ky, iw0 = ow0 + kx;
            int ih1 = oh1 + ky, iw1 = ow1 + kx;
            ti0[t] = (ih0 >= 0 && ih0 < H_ && iw0 >= 0 && iw0 < W_) ? ih0 * W_ + iw0 : -1;
            ti1[t] = (ih1 >= 0 && ih1 < H_ && iw1 >= 0 && iw1 < W_) ? ih1 * W_ + iw1 : -1;
        }
    }

    float acc0[OCH_], acc1[OCH_];
    #pragma unroll
    for (int o = 0; o < OCH_; ++o) { float bo = bias[ob + o]; acc0[o] = bo; acc1[o] = bo; }

    for (int c = 0; c < CI_; ++c) {
        const float* plane = (c < C_) ? (x + ((size_t)b * C_ + c) * HW_)
                                      : (depth + (size_t)b * HW_);
        float v0[KK_], v1[KK_];
        #pragma unroll
        for (int t = 0; t < KK_; ++t) {
            v0[t] = (ti0[t] >= 0) ? plane[ti0[t]] : 0.f;
            v1[t] = (ti1[t] >= 0) ? plane[ti1[t]] : 0.f;
        }
        #pragma unroll
        for (int t = 0; t < KK_; ++t) {
            const float* wp = &w_s[(c * KK_ + t) * WPITCH_];
            float4 wa = *reinterpret_cast<const float4*>(wp);
            float4 wb = *reinterpret_cast<const float4*>(wp + 4);
            float  wc = wp[8];
            acc0[0] = fmaf(v0[t], wa.x, acc0[0]);
            acc0[1] = fmaf(v0[t], wa.y, acc0[1]);
            acc0[2] = fmaf(v0[t], wa.z, acc0[2]);
            acc0[3] = fmaf(v0[t], wa.w, acc0[3]);
            acc0[4] = fmaf(v0[t], wb.x, acc0[4]);
            acc0[5] = fmaf(v0[t], wb.y, acc0[5]);
            acc0[6] = fmaf(v0[t], wb.z, acc0[6]);
            acc0[7] = fmaf(v0[t], wb.w, acc0[7]);
            acc0[8] = fmaf(v0[t], wc,   acc0[8]);
            acc1[0] = fmaf(v1[t], wa.x, acc1[0]);
            acc1[1] = fmaf(v1[t], wa.y, acc1[1]);
            acc1[2] = fmaf(v1[t], wa.z, acc1[2]);
            acc1[3] = fmaf(v1[t], wa.w, acc1[3]);
            acc1[4] = fmaf(v1[t], wb.x, acc1[4]);
            acc1[5] = fmaf(v1[t], wb.y, acc1[5]);
            acc1[6] = fmaf(v1[t], wb.z, acc1[6]);
            acc1[7] = fmaf(v1[t], wb.w, acc1[7]);
            acc1[8] = fmaf(v1[t], wc,   acc1[8]);
        }
    }

    #pragma unroll
    for (int o = 0; o < OCH_; ++o) {
        g_off[((size_t)b * OC_ + ob + o) * HW_ + p0] = acc0[o];
        g_off[((size_t)b * OC_ + ob + o) * HW_ + p1] = acc1[o];
    }
}

// ---------------------------------------------------------------------------
// Kernel 4: fused bilinear gather + mma.sync bf16 GEMM (3-term hi/lo split).
// Block: 128 px (M) x 64 oc (N), 256 threads / 8 warps (4 pxg x 2 ocg).
// Double-buffered A, taps precomputed, one sync per kk. Dynamic smem 87.5 KB.
// ---------------------------------------------------------------------------
#define APITCH_ 72
#define MPX_    128
#define ATILE_  (MPX_ * APITCH_)            // uint16 elems per tile
#define SM_AHI  0
#define SM_ALO  (2 * ATILE_ * 2)            // bytes: 36864
#define SM_TIDX (SM_ALO + 2 * ATILE_ * 2)   // 73728
#define SM_TA   (SM_TIDX + KK_ * MPX_ * 4)  // 78336
#define SM_TOT  (SM_TA + KK_ * MPX_ * 8)    // 87552

struct __align__(8) TapA { float ax, ay; };

__global__ __launch_bounds__(256) void fused_mma_kernel(float* __restrict__ out)
{
    extern __shared__ char sm[];
    uint16_t* Ahi = reinterpret_cast<uint16_t*>(sm + SM_AHI);   // [2][ATILE_]
    uint16_t* Alo = reinterpret_cast<uint16_t*>(sm + SM_ALO);   // [2][ATILE_]
    int*  tap_idx = reinterpret_cast<int*>(sm + SM_TIDX);       // [KK_][MPX_]
    TapA* tap_a   = reinterpret_cast<TapA*>(sm + SM_TA);        // [KK_][MPX_]

    const int tid  = threadIdx.x;
    const int wid  = tid >> 5;
    const int lane = tid & 31;
    const int b    = blockIdx.y;
    const int pix0 = blockIdx.x * MPX_;

    const int ocg = wid & 1;    // 0/1: oc group (32 oc)
    const int pxg = wid >> 1;   // 0..3: pixel group (32 px)

    float acc[2][4][4];
    #pragma unroll
    for (int mi = 0; mi < 2; ++mi)
        #pragma unroll
        for (int ni = 0; ni < 4; ++ni)
            #pragma unroll
            for (int r = 0; r < 4; ++r) acc[mi][ni][r] = 0.f;

    const float* xb = g_xp + (size_t)b * HPWP_ * C_;
    const int cg = tid & 15;    // channel group (4 ch)
    const int pb = tid >> 4;    // 0..15

    // --- phase 0: all taps (9 kk x 128 px) ---
    for (int e = tid; e < KK_ * MPX_; e += 256) {
        int kk = e >> 7;
        int p  = e & 127;
        int pix = pix0 + p;
        int oh = pix / W_, ow = pix % W_;
        float ox = g_off[((size_t)b * OC_ + kk) * HW_ + pix];
        float oy = g_off[((size_t)b * OC_ + KK_ + kk) * HW_ + pix];
        float cx = (float)(oh + kk / 3) + ox;
        float cy = (float)(ow + kk % 3) + oy;
        cx = fminf(fmaxf(cx, 0.f), (float)(HP_ - 1));
        cy = fminf(fmaxf(cy, 0.f), (float)(WP_ - 1));
        int tlx = (int)floorf(cx); tlx = min(max(tlx, 0), HP_ - 2);
        int tly = (int)floorf(cy); tly = min(max(tly, 0), WP_ - 2);
        tap_idx[kk * MPX_ + p] = tlx * WP_ + tly;
        tap_a[kk * MPX_ + p].ax = cx - (float)tlx;
        tap_a[kk * MPX_ + p].ay = cy - (float)tly;
    }
    __syncthreads();

    auto gather = [&](int kk, int buf) {
        #pragma unroll 2
        for (int i = 0; i < 8; ++i) {
            int p = pb + 16 * i;
            int idx = tap_idx[kk * MPX_ + p];
            TapA a = tap_a[kk * MPX_ + p];
            const float4* q = reinterpret_cast<const float4*>(xb + (size_t)idx * C_) + cg;
            float4 x00 = q[0];
            float4 x01 = q[16];
            float4 x10 = q[WP_ * 16];
            float4 x11 = q[(WP_ + 1) * 16];
            float4 v;
            {
                float r0, r1;
                r0 = fmaf(a.ay, x01.x - x00.x, x00.x);
                r1 = fmaf(a.ay, x11.x - x10.x, x10.x);
                v.x = fmaf(a.ax, r1 - r0, r0);
                r0 = fmaf(a.ay, x01.y - x00.y, x00.y);
                r1 = fmaf(a.ay, x11.y - x10.y, x10.y);
                v.y = fmaf(a.ax, r1 - r0, r0);
                r0 = fmaf(a.ay, x01.z - x00.z, x00.z);
                r1 = fmaf(a.ay, x11.z - x10.z, x10.z);
                v.z = fmaf(a.ax, r1 - r0, r0);
                r0 = fmaf(a.ay, x01.w - x00.w, x00.w);
                r1 = fmaf(a.ay, x11.w - x10.w, x10.w);
                v.w = fmaf(a.ax, r1 - r0, r0);
            }
            uint32_t h01 = cvt_bf16x2(v.y, v.x);
            uint32_t h23 = cvt_bf16x2(v.w, v.z);
            float l0 = v.x - __uint_as_float(h01 << 16);
            float l1 = v.y - __uint_as_float(h01 & 0xFFFF0000u);
            float l2 = v.z - __uint_as_float(h23 << 16);
            float l3 = v.w - __uint_as_float(h23 & 0xFFFF0000u);
            uint32_t q01 = cvt_bf16x2(l1, l0);
            uint32_t q23 = cvt_bf16x2(l3, l2);
            int eo = buf * ATILE_ + p * APITCH_ + cg * 4;
            *reinterpret_cast<uint2*>(&Ahi[eo]) = make_uint2(h01, h23);
            *reinterpret_cast<uint2*>(&Alo[eo]) = make_uint2(q01, q23);
        }
    };

    gather(0, 0);
    __syncthreads();

    const int arow = pxg * 32 + (lane >> 2);
    const int akol = (lane & 3) * 2;
    const int brow = ocg * 32 + (lane >> 2);

    for (int kk = 0; kk < KK_; ++kk) {
        const int buf = kk & 1;
        const uint16_t* wh = g_wtbh + kk * (C_*C_);
        const uint16_t* wl = g_wtbl + kk * (C_*C_);

        #pragma unroll
        for (int ki = 0; ki < 4; ++ki) {
            const int k0 = ki * 16 + akol;
            uint32_t ah[2][4], al[2][4];
            #pragma unroll
            for (int mi = 0; mi < 2; ++mi) {
                int r0 = buf * ATILE_ + (arow + mi * 16) * APITCH_ + k0;
                int r1 = r0 + 8 * APITCH_;
                ah[mi][0] = *reinterpret_cast<const uint32_t*>(&Ahi[r0]);
                ah[mi][1] = *reinterpret_cast<const uint32_t*>(&Ahi[r1]);
                ah[mi][2] = *reinterpret_cast<const uint32_t*>(&Ahi[r0 + 8]);
                ah[mi][3] = *reinterpret_cast<const uint32_t*>(&Ahi[r1 + 8]);
                al[mi][0] = *reinterpret_cast<const uint32_t*>(&Alo[r0]);
                al[mi][1] = *reinterpret_cast<const uint32_t*>(&Alo[r1]);
                al[mi][2] = *reinterpret_cast<const uint32_t*>(&Alo[r0 + 8]);
                al[mi][3] = *reinterpret_cast<const uint32_t*>(&Alo[r1 + 8]);
            }
            #pragma unroll
            for (int ni = 0; ni < 4; ++ni) {
                int boff = (brow + ni * 8) * C_ + k0;
                uint32_t bh0 = *reinterpret_cast<const uint32_t*>(wh + boff);
                uint32_t bh1 = *reinterpret_cast<const uint32_t*>(wh + boff + 8);
                uint32_t bl0 = *reinterpret_cast<const uint32_t*>(wl + boff);
                uint32_t bl1 = *reinterpret_cast<const uint32_t*>(wl + boff + 8);
                #pragma unroll
                for (int mi = 0; mi < 2; ++mi) {
                    float* d = acc[mi][ni];
                    mma16816(d[0], d[1], d[2], d[3],
                             ah[mi][0], ah[mi][1], ah[mi][2], ah[mi][3], bh0, bh1);
                    mma16816(d[0], d[1], d[2], d[3],
                             al[mi][0], al[mi][1], al[mi][2], al[mi][3], bh0, bh1);
                    mma16816(d[0], d[1], d[2], d[3],
                             ah[mi][0], ah[mi][1], ah[mi][2], ah[mi][3], bl0, bl1);
                }
            }
        }
        if (kk + 1 < KK_) gather(kk + 1, buf ^ 1);
        __syncthreads();
    }

    // --- epilogue: D fragment -> out[b][oc][pix] ---
    #pragma unroll
    for (int mi = 0; mi < 2; ++mi) {
        int px = pix0 + pxg * 32 + mi * 16 + (lane >> 2);
        #pragma unroll
        for (int ni = 0; ni < 4; ++ni) {
            int oc = ocg * 32 + ni * 8 + (lane & 3) * 2;
            float* o0 = out + ((size_t)b * C_ + oc) * HW_;
            float* o1 = out + ((size_t)b * C_ + oc + 1) * HW_;
            o0[px]     = acc[mi][ni][0];
            o1[px]     = acc[mi][ni][1];
            o0[px + 8] = acc[mi][ni][2];
            o1[px + 8] = acc[mi][ni][3];
        }
    }
}

// ---------------------------------------------------------------------------
// Launch
// ---------------------------------------------------------------------------
extern "C" void kernel_launch(void* const* d_in, const int* in_sizes, int n_in,
                              void* d_out, int out_size) {
    const float* x      = (const float*)d_in[0];
    const float* depth  = (const float*)d_in[1];
    const float* w_off  = (const float*)d_in[2];
    const float* bias   = (const float*)d_in[3];
    const float* weight = (const float*)d_in[4];
    float* out = (float*)d_out;

    {
        dim3 grid(144, 2);   // 144*256 = 36864 >= both job sizes
        prep_kernel<<<grid, 256>>>(weight);
    }
    {
        dim3 grid(HW_ / 32, B_);
        nhwc_kernel<<<grid, 256>>>(x);
    }
    {
        dim3 grid(HW_ / 512, 2, B_);
        offconv_kernel<<<grid, 256>>>(x, depth, w_off, bias);
    }
    {
        static bool attr_set = false;
        if (!attr_set) {
            cudaFuncSetAttribute(fused_mma_kernel,
                                 cudaFuncAttributeMaxDynamicSharedMemorySize, SM_TOT);
            attr_set = true;
        }
        dim3 grid(HW_ / MPX_, B_);
        fused_mma_kernel<<<grid, 256, SM_TOT>>>(out);
    }
}

// round 10
// speedup vs baseline: 2.5114x; 1.1835x over previous
#include <cuda_runtime.h>
#include <cuda_bf16.h>
#include <cstdint>
#include <cstring>

// Problem constants
#define B_   2
#define C_   64
#define H_   192
#define W_   192
#define HW_  (H_*W_)          // 36864
#define KK_  9
#define HP_  194
#define WP_  194
#define HPWP_ (HP_*WP_)       // 37636
#define CI_  65               // C+1
#define OC_  18               // 2*KK
#define OCH_ 9                // oc per offconv block

// Scratch (device globals)
__device__ float    g_xp  [B_*HPWP_*C_];     // padded x, NHWC  (~19.3 MB)
__device__ float    g_off [B_*OC_*HW_];      // offsets (~5.3 MB)
__device__ uint16_t g_wtbh[KK_*C_*C_];       // fused weight hi bf16, [kk][oc][c]
__device__ uint16_t g_wtbl[KK_*C_*C_];       // fused weight lo bf16

// ---------------------------------------------------------------------------
// helpers
// ---------------------------------------------------------------------------
__device__ __forceinline__ uint32_t cvt_bf16x2(float hi, float lo) {
    uint32_t r;
    asm("cvt.rn.satfinite.bf16x2.f32 %0, %1, %2;" : "=r"(r) : "f"(hi), "f"(lo));
    return r;
}

__device__ __forceinline__ void mma16816(float& d0, float& d1, float& d2, float& d3,
                                         uint32_t a0, uint32_t a1, uint32_t a2, uint32_t a3,
                                         uint32_t b0, uint32_t b1) {
    asm volatile("mma.sync.aligned.m16n8k16.row.col.f32.bf16.bf16.f32 "
                 "{%0,%1,%2,%3},{%4,%5,%6,%7},{%8,%9},{%0,%1,%2,%3};"
                 : "+f"(d0), "+f"(d1), "+f"(d2), "+f"(d3)
                 : "r"(a0), "r"(a1), "r"(a2), "r"(a3), "r"(b0), "r"(b1));
}

// ---------------------------------------------------------------------------
// Kernel 1: merged prep — job y=0: pad border of g_xp; y=1: fused weight hi/lo
// ---------------------------------------------------------------------------
#define NBORD_ (2*WP_ + 2*(HP_-2))   // 772
__global__ void prep_kernel(const float* __restrict__ w) {
    int i = blockIdx.x * blockDim.x + threadIdx.x;
    int job = blockIdx.y;
    if (job == 0) {
        if (i >= B_ * NBORD_ * 16) return;
        int b   = i / (NBORD_ * 16);
        int r   = i % (NBORD_ * 16);
        int pix = r >> 4;
        int cq  = r & 15;
        int ph, pw;
        if (pix < WP_)            { ph = 0;        pw = pix; }
        else if (pix < 2*WP_)     { ph = HP_ - 1;  pw = pix - WP_; }
        else if (pix < 2*WP_ + (HP_-2)) { ph = pix - 2*WP_ + 1;  pw = 0; }
        else                      { ph = pix - (2*WP_ + (HP_-2)) + 1; pw = WP_ - 1; }
        reinterpret_cast<float4*>(g_xp + ((size_t)b * HPWP_ + ph * WP_ + pw) * C_)[cq] =
            make_float4(0.f, 0.f, 0.f, 0.f);
    } else {
        if (i >= KK_*C_*C_) return;
        int kk = i / (C_*C_);
        int oc = (i >> 6) & 63;
        int c  = i & 63;
        float v = w[oc * 576 + c * KK_ + kk];
        __nv_bfloat16 h = __float2bfloat16(v);
        float hf = __bfloat162float(h);
        __nv_bfloat16 l = __float2bfloat16(v - hf);
        uint16_t hb, lb;
        memcpy(&hb, &h, 2); memcpy(&lb, &l, 2);
        g_wtbh[(kk * C_ + oc) * C_ + c] = hb;
        g_wtbl[(kk * C_ + oc) * C_ + c] = lb;
    }
}

// ---------------------------------------------------------------------------
// Kernel 2: NCHW -> padded NHWC transpose (interior)
// ---------------------------------------------------------------------------
__global__ __launch_bounds__(256) void nhwc_kernel(const float* __restrict__ x) {
    __shared__ float tile[C_][33];
    const int tid = threadIdx.x;
    const int b   = blockIdx.y;
    const int pix0 = blockIdx.x * 32;

    {
        int ty = tid >> 5, tx = tid & 31;
        #pragma unroll
        for (int c0 = 0; c0 < C_; c0 += 8)
            tile[c0 + ty][tx] = x[((size_t)b * C_ + c0 + ty) * HW_ + pix0 + tx];
    }
    __syncthreads();
    {
        int pi = tid >> 6, c = tid & 63;
        #pragma unroll
        for (int j = 0; j < 8; ++j) {
            int pix = pix0 + j * 4 + pi;
            int ph = pix / W_ + 1, pw = pix % W_ + 1;
            g_xp[((size_t)b * HPWP_ + ph * WP_ + pw) * C_ + c] = tile[c][j * 4 + pi];
        }
    }
}

// ---------------------------------------------------------------------------
// Kernel 3: offset-predicting conv (R6 proven version).
// ---------------------------------------------------------------------------
#define WPITCH_ 12
__global__ __launch_bounds__(256) void offconv_kernel(
    const float* __restrict__ x, const float* __restrict__ depth,
    const float* __restrict__ w_off, const float* __restrict__ bias)
{
    __shared__ __align__(16) float w_s[CI_*KK_*WPITCH_];   // 28080 B
    const int tid = threadIdx.x;
    const int ocg = blockIdx.y;           // 0/1
    const int b   = blockIdx.z;
    const int ob  = ocg * OCH_;

    for (int i = tid; i < CI_*KK_*OCH_; i += 256) {
        int ct = i / OCH_, o = i % OCH_;
        w_s[ct * WPITCH_ + o] = w_off[(ob + o) * (CI_*KK_) + ct];
    }
    __syncthreads();

    const int p0 = blockIdx.x * 512 + tid;
    const int p1 = p0 + 256;

    int ti0[KK_], ti1[KK_];
    {
        int oh0 = p0 / W_, ow0 = p0 % W_;
        int oh1 = p1 / W_, ow1 = p1 % W_;
        #pragma unroll
        for (int t = 0; t < KK_; ++t) {
            int ky = t / 3 - 1, kx = t % 3 - 1;
            int ih0 = oh0 + ky, iw0 = ow0 + kx;
            int ih1 = oh1 + ky, iw1 = ow1 + kx;
            ti0[t] = (ih0 >= 0 && ih0 < H_ && iw0 >= 0 && iw0 < W_) ? ih0 * W_ + iw0 : -1;
            ti1[t] = (ih1 >= 0 && ih1 < H_ && iw1 >= 0 && iw1 < W_) ? ih1 * W_ + iw1 : -1;
        }
    }

    float acc0[OCH_], acc1[OCH_];
    #pragma unroll
    for (int o = 0; o < OCH_; ++o) { float bo = bias[ob + o]; acc0[o] = bo; acc1[o] = bo; }

    for (int c = 0; c < CI_; ++c) {
        const float* plane = (c < C_) ? (x + ((size_t)b * C_ + c) * HW_)
                                      : (depth + (size_t)b * HW_);
        float v0[KK_], v1[KK_];
        #pragma unroll
        for (int t = 0; t < KK_; ++t) {
            v0[t] = (ti0[t] >= 0) ? plane[ti0[t]] : 0.f;
            v1[t] = (ti1[t] >= 0) ? plane[ti1[t]] : 0.f;
        }
        #pragma unroll
        for (int t = 0; t < KK_; ++t) {
            const float* wp = &w_s[(c * KK_ + t) * WPITCH_];
            float4 wa = *reinterpret_cast<const float4*>(wp);
            float4 wb = *reinterpret_cast<const float4*>(wp + 4);
            float  wc = wp[8];
            acc0[0] = fmaf(v0[t], wa.x, acc0[0]);
            acc0[1] = fmaf(v0[t], wa.y, acc0[1]);
            acc0[2] = fmaf(v0[t], wa.z, acc0[2]);
            acc0[3] = fmaf(v0[t], wa.w, acc0[3]);
            acc0[4] = fmaf(v0[t], wb.x, acc0[4]);
            acc0[5] = fmaf(v0[t], wb.y, acc0[5]);
            acc0[6] = fmaf(v0[t], wb.z, acc0[6]);
            acc0[7] = fmaf(v0[t], wb.w, acc0[7]);
            acc0[8] = fmaf(v0[t], wc,   acc0[8]);
            acc1[0] = fmaf(v1[t], wa.x, acc1[0]);
            acc1[1] = fmaf(v1[t], wa.y, acc1[1]);
            acc1[2] = fmaf(v1[t], wa.z, acc1[2]);
            acc1[3] = fmaf(v1[t], wa.w, acc1[3]);
            acc1[4] = fmaf(v1[t], wb.x, acc1[4]);
            acc1[5] = fmaf(v1[t], wb.y, acc1[5]);
            acc1[6] = fmaf(v1[t], wb.z, acc1[6]);
            acc1[7] = fmaf(v1[t], wb.w, acc1[7]);
            acc1[8] = fmaf(v1[t], wc,   acc1[8]);
        }
    }

    #pragma unroll
    for (int o = 0; o < OCH_; ++o) {
        g_off[((size_t)b * OC_ + ob + o) * HW_ + p0] = acc0[o];
        g_off[((size_t)b * OC_ + ob + o) * HW_ + p1] = acc1[o];
    }
}

// ---------------------------------------------------------------------------
// Kernel 4: fused bilinear gather + mma.sync bf16 GEMM (3-term hi/lo split).
// Block: 64 px x 64 oc, 128 threads / 4 warps. A double-buffered; B chunk
// STAGED in smem (pitch 72, conflict-free LDS fragments). Two syncs per kk.
// Dynamic smem 60.75 KB -> 3 blocks/SM.
// ---------------------------------------------------------------------------
#define APITCH_ 72
#define ATILE_  (64 * APITCH_)              // 4608 uint16
#define SM_AHI  0
#define SM_ALO  (2 * ATILE_ * 2)            // 18432
#define SM_BHI  (SM_ALO + 2 * ATILE_ * 2)   // 36864
#define SM_BLO  (SM_BHI + ATILE_ * 2)       // 46080
#define SM_TIDX (SM_BLO + ATILE_ * 2)       // 55296
#define SM_TA   (SM_TIDX + KK_ * 64 * 4)    // 57600
#define SM_TOT  (SM_TA + KK_ * 64 * 8)      // 62208

struct __align__(8) TapA { float ax, ay; };

__global__ __launch_bounds__(128) void fused_mma_kernel(float* __restrict__ out)
{
    extern __shared__ char sm[];
    uint16_t* Ahi = reinterpret_cast<uint16_t*>(sm + SM_AHI);   // [2][ATILE_]
    uint16_t* Alo = reinterpret_cast<uint16_t*>(sm + SM_ALO);   // [2][ATILE_]
    uint16_t* Bhi = reinterpret_cast<uint16_t*>(sm + SM_BHI);   // [64*72]
    uint16_t* Blo = reinterpret_cast<uint16_t*>(sm + SM_BLO);   // [64*72]
    int*  tap_idx = reinterpret_cast<int*>(sm + SM_TIDX);       // [KK_][64]
    TapA* tap_a   = reinterpret_cast<TapA*>(sm + SM_TA);        // [KK_][64]

    const int tid  = threadIdx.x;
    const int wid  = tid >> 5;
    const int lane = tid & 31;
    const int b    = blockIdx.y;
    const int pix0 = blockIdx.x * 64;

    const int pxg = wid & 1;    // 0/1: pixel group (32 px)
    const int ocg = wid >> 1;   // 0/1: oc group (32 oc)

    float acc[2][4][4];
    #pragma unroll
    for (int mi = 0; mi < 2; ++mi)
        #pragma unroll
        for (int ni = 0; ni < 4; ++ni)
            #pragma unroll
            for (int r = 0; r < 4; ++r) acc[mi][ni][r] = 0.f;

    const float* xb = g_xp + (size_t)b * HPWP_ * C_;
    const int cg = tid & 15;
    const int pb = tid >> 4;

    // --- taps for all 9 kk ---
    for (int e = tid; e < KK_ * 64; e += 128) {
        int kk = e >> 6;
        int p  = e & 63;
        int pix = pix0 + p;
        int oh = pix / W_, ow = pix % W_;
        float ox = g_off[((size_t)b * OC_ + kk) * HW_ + pix];
        float oy = g_off[((size_t)b * OC_ + KK_ + kk) * HW_ + pix];
        float cx = (float)(oh + kk / 3) + ox;
        float cy = (float)(ow + kk % 3) + oy;
        cx = fminf(fmaxf(cx, 0.f), (float)(HP_ - 1));
        cy = fminf(fmaxf(cy, 0.f), (float)(WP_ - 1));
        int tlx = (int)floorf(cx); tlx = min(max(tlx, 0), HP_ - 2);
        int tly = (int)floorf(cy); tly = min(max(tly, 0), WP_ - 2);
        tap_idx[e] = tlx * WP_ + tly;
        tap_a[e].ax = cx - (float)tlx;
        tap_a[e].ay = cy - (float)tly;
    }
    __syncthreads();

    auto gather = [&](int kk, int buf) {
        #pragma unroll 2
        for (int i = 0; i < 8; ++i) {
            int p = pb + 8 * i;
            int idx = tap_idx[kk * 64 + p];
            TapA a = tap_a[kk * 64 + p];
            const float4* q = reinterpret_cast<const float4*>(xb + (size_t)idx * C_) + cg;
            float4 x00 = q[0];
            float4 x01 = q[16];
            float4 x10 = q[WP_ * 16];
            float4 x11 = q[(WP_ + 1) * 16];
            float4 v;
            {
                float r0, r1;
                r0 = fmaf(a.ay, x01.x - x00.x, x00.x);
                r1 = fmaf(a.ay, x11.x - x10.x, x10.x);
                v.x = fmaf(a.ax, r1 - r0, r0);
                r0 = fmaf(a.ay, x01.y - x00.y, x00.y);
                r1 = fmaf(a.ay, x11.y - x10.y, x10.y);
                v.y = fmaf(a.ax, r1 - r0, r0);
                r0 = fmaf(a.ay, x01.z - x00.z, x00.z);
                r1 = fmaf(a.ay, x11.z - x10.z, x10.z);
                v.z = fmaf(a.ax, r1 - r0, r0);
                r0 = fmaf(a.ay, x01.w - x00.w, x00.w);
                r1 = fmaf(a.ay, x11.w - x10.w, x10.w);
                v.w = fmaf(a.ax, r1 - r0, r0);
            }
            uint32_t h01 = cvt_bf16x2(v.y, v.x);
            uint32_t h23 = cvt_bf16x2(v.w, v.z);
            float l0 = v.x - __uint_as_float(h01 << 16);
            float l1 = v.y - __uint_as_float(h01 & 0xFFFF0000u);
            float l2 = v.z - __uint_as_float(h23 << 16);
            float l3 = v.w - __uint_as_float(h23 & 0xFFFF0000u);
            uint32_t q01 = cvt_bf16x2(l1, l0);
            uint32_t q23 = cvt_bf16x2(l3, l2);
            int eo = buf * ATILE_ + p * APITCH_ + cg * 4;
            *reinterpret_cast<uint2*>(&Ahi[eo]) = make_uint2(h01, h23);
            *reinterpret_cast<uint2*>(&Alo[eo]) = make_uint2(q01, q23);
        }
    };

    // stage B chunk kk into smem (coalesced uint2 copy, pitch 72)
    auto stageB = [&](int kk) {
        const uint2* sh = reinterpret_cast<const uint2*>(g_wtbh + kk * (C_*C_));
        const uint2* sl = reinterpret_cast<const uint2*>(g_wtbl + kk * (C_*C_));
        #pragma unroll
        for (int e = tid; e < 1024; e += 128) {
            int oc = e >> 4, c4 = e & 15;
            int doff = oc * APITCH_ + c4 * 4;
            *reinterpret_cast<uint2*>(&Bhi[doff]) = sh[e];
            *reinterpret_cast<uint2*>(&Blo[doff]) = sl[e];
        }
    };

    gather(0, 0);
    stageB(0);
    __syncthreads();

    const int arow = pxg * 32 + (lane >> 2);
    const int akol = (lane & 3) * 2;
    const int brow = ocg * 32 + (lane >> 2);

    for (int kk = 0; kk < KK_; ++kk) {
        const int buf = kk & 1;

        #pragma unroll
        for (int ki = 0; ki < 4; ++ki) {
            const int k0 = ki * 16 + akol;
            uint32_t ah[2][4], al[2][4];
            #pragma unroll
            for (int mi = 0; mi < 2; ++mi) {
                int r0 = buf * ATILE_ + (arow + mi * 16) * APITCH_ + k0;
                int r1 = r0 + 8 * APITCH_;
                ah[mi][0] = *reinterpret_cast<const uint32_t*>(&Ahi[r0]);
                ah[mi][1] = *reinterpret_cast<const uint32_t*>(&Ahi[r1]);
                ah[mi][2] = *reinterpret_cast<const uint32_t*>(&Ahi[r0 + 8]);
                ah[mi][3] = *reinterpret_cast<const uint32_t*>(&Ahi[r1 + 8]);
                al[mi][0] = *reinterpret_cast<const uint32_t*>(&Alo[r0]);
                al[mi][1] = *reinterpret_cast<const uint32_t*>(&Alo[r1]);
                al[mi][2] = *reinterpret_cast<const uint32_t*>(&Alo[r0 + 8]);
                al[mi][3] = *reinterpret_cast<const uint32_t*>(&Alo[r1 + 8]);
            }
            #pragma unroll
            for (int ni = 0; ni < 4; ++ni) {
                int boff = (brow + ni * 8) * APITCH_ + k0;
                uint32_t bh0 = *reinterpret_cast<const uint32_t*>(&Bhi[boff]);
                uint32_t bh1 = *reinterpret_cast<const uint32_t*>(&Bhi[boff + 8]);
                uint32_t bl0 = *reinterpret_cast<const uint32_t*>(&Blo[boff]);
                uint32_t bl1 = *reinterpret_cast<const uint32_t*>(&Blo[boff + 8]);
                #pragma unroll
                for (int mi = 0; mi < 2; ++mi) {
                    float* d = acc[mi][ni];
                    mma16816(d[0], d[1], d[2], d[3],
                             ah[mi][0], ah[mi][1], ah[mi][2], ah[mi][3], bh0, bh1);
                    mma16816(d[0], d[1], d[2], d[3],
                             al[mi][0], al[mi][1], al[mi][2], al[mi][3], bh0, bh1);
                    mma16816(d[0], d[1], d[2], d[3],
                             ah[mi][0], ah[mi][1], ah[mi][2], ah[mi][3], bl0, bl1);
                }
            }
        }
        if (kk + 1 < KK_) {
            gather(kk + 1, buf ^ 1);
            __syncthreads();           // all warps done with mma(kk) -> B free
            stageB(kk + 1);
            __syncthreads();           // B(kk+1) + A(kk+1) visible
        }
    }

    // --- epilogue: D fragment -> out[b][oc][pix] ---
    #pragma unroll
    for (int mi = 0; mi < 2; ++mi) {
        int px = pix0 + pxg * 32 + mi * 16 + (lane >> 2);
        #pragma unroll
        for (int ni = 0; ni < 4; ++ni) {
            int oc = ocg * 32 + ni * 8 + (lane & 3) * 2;
            float* o0 = out + ((size_t)b * C_ + oc) * HW_;
            float* o1 = out + ((size_t)b * C_ + oc + 1) * HW_;
            o0[px]     = acc[mi][ni][0];
            o1[px]     = acc[mi][ni][1];
            o0[px + 8] = acc[mi][ni][2];
            o1[px + 8] = acc[mi][ni][3];
        }
    }
}

// ---------------------------------------------------------------------------
// Launch
// ---------------------------------------------------------------------------
extern "C" void kernel_launch(void* const* d_in, const int* in_sizes, int n_in,
                              void* d_out, int out_size) {
    const float* x      = (const float*)d_in[0];
    const float* depth  = (const float*)d_in[1];
    const float* w_off  = (const float*)d_in[2];
    const float* bias   = (const float*)d_in[3];
    const float* weight = (const float*)d_in[4];
    float* out = (float*)d_out;

    {
        dim3 grid(144, 2);
        prep_kernel<<<grid, 256>>>(weight);
    }
    {
        dim3 grid(HW_ / 32, B_);
        nhwc_kernel<<<grid, 256>>>(x);
    }
    {
        dim3 grid(HW_ / 512, 2, B_);
        offconv_kernel<<<grid, 256>>>(x, depth, w_off, bias);
    }
    {
        static bool attr_set = false;
        if (!attr_set) {
            cudaFuncSetAttribute(fused_mma_kernel,
                                 cudaFuncAttributeMaxDynamicSharedMemorySize, SM_TOT);
            attr_set = true;
        }
        dim3 grid(HW_ / 64, B_);
        fused_mma_kernel<<<grid, 128, SM_TOT>>>(out);
    }
}

// round 11
// speedup vs baseline: 2.9048x; 1.1566x over previous
#include <cuda_runtime.h>
#include <cuda_bf16.h>
#include <cstdint>
#include <cstring>

// Problem constants
#define B_   2
#define C_   64
#define H_   192
#define W_   192
#define HW_  (H_*W_)          // 36864
#define KK_  9
#define HP_  194
#define WP_  194
#define HPWP_ (HP_*WP_)       // 37636
#define CI_  65               // C+1
#define OC_  18               // 2*KK
#define OCH_ 9                // oc per offconv block

// Scratch (device globals)
__device__ float    g_xp  [B_*HPWP_*C_];     // padded x, NHWC  (~19.3 MB)
__device__ float    g_off [B_*OC_*HW_];      // offsets (~5.3 MB)
__device__ uint16_t g_wtbh[KK_*C_*C_];       // fused weight hi bf16, [kk][oc][c]
__device__ uint16_t g_wtbl[KK_*C_*C_];       // fused weight lo bf16

// ---------------------------------------------------------------------------
// helpers
// ---------------------------------------------------------------------------
__device__ __forceinline__ uint32_t cvt_bf16x2(float hi, float lo) {
    uint32_t r;
    asm("cvt.rn.satfinite.bf16x2.f32 %0, %1, %2;" : "=r"(r) : "f"(hi), "f"(lo));
    return r;
}

__device__ __forceinline__ void mma16816(float& d0, float& d1, float& d2, float& d3,
                                         uint32_t a0, uint32_t a1, uint32_t a2, uint32_t a3,
                                         uint32_t b0, uint32_t b1) {
    asm volatile("mma.sync.aligned.m16n8k16.row.col.f32.bf16.bf16.f32 "
                 "{%0,%1,%2,%3},{%4,%5,%6,%7},{%8,%9},{%0,%1,%2,%3};"
                 : "+f"(d0), "+f"(d1), "+f"(d2), "+f"(d3)
                 : "r"(a0), "r"(a1), "r"(a2), "r"(a3), "r"(b0), "r"(b1));
}

// ---------------------------------------------------------------------------
// Kernel 1: merged prep — job y=0: pad border of g_xp; y=1: fused weight hi/lo
// ---------------------------------------------------------------------------
#define NBORD_ (2*WP_ + 2*(HP_-2))   // 772
__global__ void prep_kernel(const float* __restrict__ w) {
    int i = blockIdx.x * blockDim.x + threadIdx.x;
    int job = blockIdx.y;
    if (job == 0) {
        if (i >= B_ * NBORD_ * 16) return;
        int b   = i / (NBORD_ * 16);
        int r   = i % (NBORD_ * 16);
        int pix = r >> 4;
        int cq  = r & 15;
        int ph, pw;
        if (pix < WP_)            { ph = 0;        pw = pix; }
        else if (pix < 2*WP_)     { ph = HP_ - 1;  pw = pix - WP_; }
        else if (pix < 2*WP_ + (HP_-2)) { ph = pix - 2*WP_ + 1;  pw = 0; }
        else                      { ph = pix - (2*WP_ + (HP_-2)) + 1; pw = WP_ - 1; }
        reinterpret_cast<float4*>(g_xp + ((size_t)b * HPWP_ + ph * WP_ + pw) * C_)[cq] =
            make_float4(0.f, 0.f, 0.f, 0.f);
    } else {
        if (i >= KK_*C_*C_) return;
        int kk = i / (C_*C_);
        int oc = (i >> 6) & 63;
        int c  = i & 63;
        float v = w[oc * 576 + c * KK_ + kk];
        __nv_bfloat16 h = __float2bfloat16(v);
        float hf = __bfloat162float(h);
        __nv_bfloat16 l = __float2bfloat16(v - hf);
        uint16_t hb, lb;
        memcpy(&hb, &h, 2); memcpy(&lb, &l, 2);
        g_wtbh[(kk * C_ + oc) * C_ + c] = hb;
        g_wtbl[(kk * C_ + oc) * C_ + c] = lb;
    }
}

// ---------------------------------------------------------------------------
// Kernel 2: NCHW -> padded NHWC transpose (interior)
// ---------------------------------------------------------------------------
__global__ __launch_bounds__(256) void nhwc_kernel(const float* __restrict__ x) {
    __shared__ float tile[C_][33];
    const int tid = threadIdx.x;
    const int b   = blockIdx.y;
    const int pix0 = blockIdx.x * 32;

    {
        int ty = tid >> 5, tx = tid & 31;
        #pragma unroll
        for (int c0 = 0; c0 < C_; c0 += 8)
            tile[c0 + ty][tx] = x[((size_t)b * C_ + c0 + ty) * HW_ + pix0 + tx];
    }
    __syncthreads();
    {
        int pi = tid >> 6, c = tid & 63;
        #pragma unroll
        for (int j = 0; j < 8; ++j) {
            int pix = pix0 + j * 4 + pi;
            int ph = pix / W_ + 1, pw = pix % W_ + 1;
            g_xp[((size_t)b * HPWP_ + ph * WP_ + pw) * C_ + c] = tile[c][j * 4 + pi];
        }
    }
}

// ---------------------------------------------------------------------------
// Kernel 3: offset-predicting conv (R6 proven version).
// ---------------------------------------------------------------------------
#define WPITCH_ 12
__global__ __launch_bounds__(256) void offconv_kernel(
    const float* __restrict__ x, const float* __restrict__ depth,
    const float* __restrict__ w_off, const float* __restrict__ bias)
{
    __shared__ __align__(16) float w_s[CI_*KK_*WPITCH_];   // 28080 B
    const int tid = threadIdx.x;
    const int ocg = blockIdx.y;           // 0/1
    const int b   = blockIdx.z;
    const int ob  = ocg * OCH_;

    for (int i = tid; i < CI_*KK_*OCH_; i += 256) {
        int ct = i / OCH_, o = i % OCH_;
        w_s[ct * WPITCH_ + o] = w_off[(ob + o) * (CI_*KK_) + ct];
    }
    __syncthreads();

    const int p0 = blockIdx.x * 512 + tid;
    const int p1 = p0 + 256;

    int ti0[KK_], ti1[KK_];
    {
        int oh0 = p0 / W_, ow0 = p0 % W_;
        int oh1 = p1 / W_, ow1 = p1 % W_;
        #pragma unroll
        for (int t = 0; t < KK_; ++t) {
            int ky = t / 3 - 1, kx = t % 3 - 1;
            int ih0 = oh0 + ky, iw0 = ow0 + kx;
            int ih1 = oh1 + ky, iw1 = ow1 + kx;
            ti0[t] = (ih0 >= 0 && ih0 < H_ && iw0 >= 0 && iw0 < W_) ? ih0 * W_ + iw0 : -1;
            ti1[t] = (ih1 >= 0 && ih1 < H_ && iw1 >= 0 && iw1 < W_) ? ih1 * W_ + iw1 : -1;
        }
    }

    float acc0[OCH_], acc1[OCH_];
    #pragma unroll
    for (int o = 0; o < OCH_; ++o) { float bo = bias[ob + o]; acc0[o] = bo; acc1[o] = bo; }

    for (int c = 0; c < CI_; ++c) {
        const float* plane = (c < C_) ? (x + ((size_t)b * C_ + c) * HW_)
                                      : (depth + (size_t)b * HW_);
        float v0[KK_], v1[KK_];
        #pragma unroll
        for (int t = 0; t < KK_; ++t) {
            v0[t] = (ti0[t] >= 0) ? plane[ti0[t]] : 0.f;
            v1[t] = (ti1[t] >= 0) ? plane[ti1[t]] : 0.f;
        }
        #pragma unroll
        for (int t = 0; t < KK_; ++t) {
            const float* wp = &w_s[(c * KK_ + t) * WPITCH_];
            float4 wa = *reinterpret_cast<const float4*>(wp);
            float4 wb = *reinterpret_cast<const float4*>(wp + 4);
            float  wc = wp[8];
            acc0[0] = fmaf(v0[t], wa.x, acc0[0]);
            acc0[1] = fmaf(v0[t], wa.y, acc0[1]);
            acc0[2] = fmaf(v0[t], wa.z, acc0[2]);
            acc0[3] = fmaf(v0[t], wa.w, acc0[3]);
            acc0[4] = fmaf(v0[t], wb.x, acc0[4]);
            acc0[5] = fmaf(v0[t], wb.y, acc0[5]);
            acc0[6] = fmaf(v0[t], wb.z, acc0[6]);
            acc0[7] = fmaf(v0[t], wb.w, acc0[7]);
            acc0[8] = fmaf(v0[t], wc,   acc0[8]);
            acc1[0] = fmaf(v1[t], wa.x, acc1[0]);
            acc1[1] = fmaf(v1[t], wa.y, acc1[1]);
            acc1[2] = fmaf(v1[t], wa.z, acc1[2]);
            acc1[3] = fmaf(v1[t], wa.w, acc1[3]);
            acc1[4] = fmaf(v1[t], wb.x, acc1[4]);
            acc1[5] = fmaf(v1[t], wb.y, acc1[5]);
            acc1[6] = fmaf(v1[t], wb.z, acc1[6]);
            acc1[7] = fmaf(v1[t], wb.w, acc1[7]);
            acc1[8] = fmaf(v1[t], wc,   acc1[8]);
        }
    }

    #pragma unroll
    for (int o = 0; o < OCH_; ++o) {
        g_off[((size_t)b * OC_ + ob + o) * HW_ + p0] = acc0[o];
        g_off[((size_t)b * OC_ + ob + o) * HW_ + p1] = acc1[o];
    }
}

// ---------------------------------------------------------------------------
// Kernel 4: fused bilinear gather + mma.sync bf16 GEMM (3-term hi/lo split).
// Block: 128 px x 64 oc, 256 threads / 8 warps (4 pxg x 2 ocg).
// Single-buffered A + staged B (pitch 72). 2 syncs per kk.
// Dynamic smem 67.5 KB -> 3 blocks/SM = 24 warps (37.5% occ).
// ---------------------------------------------------------------------------
#define APITCH_ 72
#define MPX_    128
#define ATILE_  (MPX_ * APITCH_)            // 9216 uint16
#define BTILE_  (C_ * APITCH_)              // 4608 uint16
#define SM_AHI  0
#define SM_ALO  (ATILE_ * 2)                // 18432
#define SM_BHI  (SM_ALO + ATILE_ * 2)       // 36864
#define SM_BLO  (SM_BHI + BTILE_ * 2)       // 46080
#define SM_TIDX (SM_BLO + BTILE_ * 2)       // 55296
#define SM_TA   (SM_TIDX + KK_ * MPX_ * 4)  // 59904
#define SM_TOT  (SM_TA + KK_ * MPX_ * 8)    // 69120

struct __align__(8) TapA { float ax, ay; };

__global__ __launch_bounds__(256) void fused_mma_kernel(float* __restrict__ out)
{
    extern __shared__ char sm[];
    uint16_t* Ahi = reinterpret_cast<uint16_t*>(sm + SM_AHI);   // [ATILE_]
    uint16_t* Alo = reinterpret_cast<uint16_t*>(sm + SM_ALO);   // [ATILE_]
    uint16_t* Bhi = reinterpret_cast<uint16_t*>(sm + SM_BHI);   // [BTILE_]
    uint16_t* Blo = reinterpret_cast<uint16_t*>(sm + SM_BLO);   // [BTILE_]
    int*  tap_idx = reinterpret_cast<int*>(sm + SM_TIDX);       // [KK_][MPX_]
    TapA* tap_a   = reinterpret_cast<TapA*>(sm + SM_TA);        // [KK_][MPX_]

    const int tid  = threadIdx.x;
    const int wid  = tid >> 5;
    const int lane = tid & 31;
    const int b    = blockIdx.y;
    const int pix0 = blockIdx.x * MPX_;

    const int ocg = wid & 1;    // 0/1: oc group (32 oc)
    const int pxg = wid >> 1;   // 0..3: pixel group (32 px)

    float acc[2][4][4];
    #pragma unroll
    for (int mi = 0; mi < 2; ++mi)
        #pragma unroll
        for (int ni = 0; ni < 4; ++ni)
            #pragma unroll
            for (int r = 0; r < 4; ++r) acc[mi][ni][r] = 0.f;

    const float* xb = g_xp + (size_t)b * HPWP_ * C_;
    const int cg = tid & 15;    // channel group (4 ch)
    const int pb = tid >> 4;    // 0..15

    // --- taps for all 9 kk x 128 px ---
    for (int e = tid; e < KK_ * MPX_; e += 256) {
        int kk = e >> 7;
        int p  = e & 127;
        int pix = pix0 + p;
        int oh = pix / W_, ow = pix % W_;
        float ox = g_off[((size_t)b * OC_ + kk) * HW_ + pix];
        float oy = g_off[((size_t)b * OC_ + KK_ + kk) * HW_ + pix];
        float cx = (float)(oh + kk / 3) + ox;
        float cy = (float)(ow + kk % 3) + oy;
        cx = fminf(fmaxf(cx, 0.f), (float)(HP_ - 1));
        cy = fminf(fmaxf(cy, 0.f), (float)(WP_ - 1));
        int tlx = (int)floorf(cx); tlx = min(max(tlx, 0), HP_ - 2);
        int tly = (int)floorf(cy); tly = min(max(tly, 0), WP_ - 2);
        tap_idx[e] = tlx * WP_ + tly;
        tap_a[e].ax = cx - (float)tlx;
        tap_a[e].ay = cy - (float)tly;
    }

    auto gather = [&](int kk) {
        #pragma unroll 2
        for (int i = 0; i < 8; ++i) {
            int p = pb + 16 * i;
            int idx = tap_idx[kk * MPX_ + p];
            TapA a = tap_a[kk * MPX_ + p];
            const float4* q = reinterpret_cast<const float4*>(xb + (size_t)idx * C_) + cg;
            float4 x00 = q[0];
            float4 x01 = q[16];
            float4 x10 = q[WP_ * 16];
            float4 x11 = q[(WP_ + 1) * 16];
            float4 v;
            {
                float r0, r1;
                r0 = fmaf(a.ay, x01.x - x00.x, x00.x);
                r1 = fmaf(a.ay, x11.x - x10.x, x10.x);
                v.x = fmaf(a.ax, r1 - r0, r0);
                r0 = fmaf(a.ay, x01.y - x00.y, x00.y);
                r1 = fmaf(a.ay, x11.y - x10.y, x10.y);
                v.y = fmaf(a.ax, r1 - r0, r0);
                r0 = fmaf(a.ay, x01.z - x00.z, x00.z);
                r1 = fmaf(a.ay, x11.z - x10.z, x10.z);
                v.z = fmaf(a.ax, r1 - r0, r0);
                r0 = fmaf(a.ay, x01.w - x00.w, x00.w);
                r1 = fmaf(a.ay, x11.w - x10.w, x10.w);
                v.w = fmaf(a.ax, r1 - r0, r0);
            }
            uint32_t h01 = cvt_bf16x2(v.y, v.x);
            uint32_t h23 = cvt_bf16x2(v.w, v.z);
            float l0 = v.x - __uint_as_float(h01 << 16);
            float l1 = v.y - __uint_as_float(h01 & 0xFFFF0000u);
            float l2 = v.z - __uint_as_float(h23 << 16);
            float l3 = v.w - __uint_as_float(h23 & 0xFFFF0000u);
            uint32_t q01 = cvt_bf16x2(l1, l0);
            uint32_t q23 = cvt_bf16x2(l3, l2);
            int eo = p * APITCH_ + cg * 4;
            *reinterpret_cast<uint2*>(&Ahi[eo]) = make_uint2(h01, h23);
            *reinterpret_cast<uint2*>(&Alo[eo]) = make_uint2(q01, q23);
        }
    };

    // stage B chunk kk into smem (coalesced uint2 copy, pitch 72)
    auto stageB = [&](int kk) {
        const uint2* sh = reinterpret_cast<const uint2*>(g_wtbh + kk * (C_*C_));
        const uint2* sl = reinterpret_cast<const uint2*>(g_wtbl + kk * (C_*C_));
        #pragma unroll
        for (int e = tid; e < 1024; e += 256) {
            int oc = e >> 4, c4 = e & 15;
            int doff = oc * APITCH_ + c4 * 4;
            *reinterpret_cast<uint2*>(&Bhi[doff]) = sh[e];
            *reinterpret_cast<uint2*>(&Blo[doff]) = sl[e];
        }
    };

    __syncthreads();            // taps visible
    gather(0);
    stageB(0);
    __syncthreads();

    const int arow = pxg * 32 + (lane >> 2);
    const int akol = (lane & 3) * 2;
    const int brow = ocg * 32 + (lane >> 2);

    for (int kk = 0; kk < KK_; ++kk) {
        #pragma unroll
        for (int ki = 0; ki < 4; ++ki) {
            const int k0 = ki * 16 + akol;
            uint32_t ah[2][4], al[2][4];
            #pragma unroll
            for (int mi = 0; mi < 2; ++mi) {
                int r0 = (arow + mi * 16) * APITCH_ + k0;
                int r1 = r0 + 8 * APITCH_;
                ah[mi][0] = *reinterpret_cast<const uint32_t*>(&Ahi[r0]);
                ah[mi][1] = *reinterpret_cast<const uint32_t*>(&Ahi[r1]);
                ah[mi][2] = *reinterpret_cast<const uint32_t*>(&Ahi[r0 + 8]);
                ah[mi][3] = *reinterpret_cast<const uint32_t*>(&Ahi[r1 + 8]);
                al[mi][0] = *reinterpret_cast<const uint32_t*>(&Alo[r0]);
                al[mi][1] = *reinterpret_cast<const uint32_t*>(&Alo[r1]);
                al[mi][2] = *reinterpret_cast<const uint32_t*>(&Alo[r0 + 8]);
                al[mi][3] = *reinterpret_cast<const uint32_t*>(&Alo[r1 + 8]);
            }
            #pragma unroll
            for (int ni = 0; ni < 4; ++ni) {
                int boff = (brow + ni * 8) * APITCH_ + k0;
                uint32_t bh0 = *reinterpret_cast<const uint32_t*>(&Bhi[boff]);
                uint32_t bh1 = *reinterpret_cast<const uint32_t*>(&Bhi[boff + 8]);
                uint32_t bl0 = *reinterpret_cast<const uint32_t*>(&Blo[boff]);
                uint32_t bl1 = *reinterpret_cast<const uint32_t*>(&Blo[boff + 8]);
                #pragma unroll
                for (int mi = 0; mi < 2; ++mi) {
                    float* d = acc[mi][ni];
                    mma16816(d[0], d[1], d[2], d[3],
                             ah[mi][0], ah[mi][1], ah[mi][2], ah[mi][3], bh0, bh1);
                    mma16816(d[0], d[1], d[2], d[3],
                             al[mi][0], al[mi][1], al[mi][2], al[mi][3], bh0, bh1);
                    mma16816(d[0], d[1], d[2], d[3],
                             ah[mi][0], ah[mi][1], ah[mi][2], ah[mi][3], bl0, bl1);
                }
            }
        }
        if (kk + 1 < KK_) {
            __syncthreads();           // mma(kk) done -> A/B free
            gather(kk + 1);
            stageB(kk + 1);
            __syncthreads();           // A(kk+1)/B(kk+1) visible
        }
    }

    // --- epilogue: D fragment -> out[b][oc][pix] ---
    #pragma unroll
    for (int mi = 0; mi < 2; ++mi) {
        int px = pix0 + pxg * 32 + mi * 16 + (lane >> 2);
        #pragma unroll
        for (int ni = 0; ni < 4; ++ni) {
            int oc = ocg * 32 + ni * 8 + (lane & 3) * 2;
            float* o0 = out + ((size_t)b * C_ + oc) * HW_;
            float* o1 = out + ((size_t)b * C_ + oc + 1) * HW_;
            o0[px]     = acc[mi][ni][0];
            o1[px]     = acc[mi][ni][1];
            o0[px + 8] = acc[mi][ni][2];
            o1[px + 8] = acc[mi][ni][3];
        }
    }
}

// ---------------------------------------------------------------------------
// Launch
// ---------------------------------------------------------------------------
extern "C" void kernel_launch(void* const* d_in, const int* in_sizes, int n_in,
                              void* d_out, int out_size) {
    const float* x      = (const float*)d_in[0];
    const float* depth  = (const float*)d_in[1];
    const float* w_off  = (const float*)d_in[2];
    const float* bias   = (const float*)d_in[3];
    const float* weight = (const float*)d_in[4];
    float* out = (float*)d_out;

    {
        dim3 grid(144, 2);
        prep_kernel<<<grid, 256>>>(weight);
    }
    {
        dim3 grid(HW_ / 32, B_);
        nhwc_kernel<<<grid, 256>>>(x);
    }
    {
        dim3 grid(HW_ / 512, 2, B_);
        offconv_kernel<<<grid, 256>>>(x, depth, w_off, bias);
    }
    {
        static bool attr_set = false;
        if (!attr_set) {
            cudaFuncSetAttribute(fused_mma_kernel,
                                 cudaFuncAttributeMaxDynamicSharedMemorySize, SM_TOT);
            attr_set = true;
        }
        dim3 grid(HW_ / MPX_, B_);
        fused_mma_kernel<<<grid, 256, SM_TOT>>>(out);
    }
}

// round 12
// speedup vs baseline: 3.0860x; 1.0624x over previous
#include <cuda_runtime.h>
#include <cuda_bf16.h>
#include <cstdint>
#include <cstring>

// Problem constants
#define B_   2
#define C_   64
#define H_   192
#define W_   192
#define HW_  (H_*W_)          // 36864
#define KK_  9
#define HP_  194
#define WP_  194
#define HPWP_ (HP_*WP_)       // 37636
#define CI_  65               // C+1
#define OC_  18               // 2*KK
#define OCH_ 9                // oc per offconv block

// Scratch (device globals)
__device__ float    g_xp  [B_*HPWP_*C_];     // padded x, NHWC  (~19.3 MB)
__device__ float    g_off [B_*OC_*HW_];      // offsets (~5.3 MB)
__device__ uint16_t g_wtbh[KK_*C_*C_];       // fused weight hi bf16, [kk][oc][c]
__device__ uint16_t g_wtbl[KK_*C_*C_];       // fused weight lo bf16

// ---------------------------------------------------------------------------
// helpers
// ---------------------------------------------------------------------------
__device__ __forceinline__ uint32_t cvt_bf16x2(float hi, float lo) {
    uint32_t r;
    asm("cvt.rn.satfinite.bf16x2.f32 %0, %1, %2;" : "=r"(r) : "f"(hi), "f"(lo));
    return r;
}

__device__ __forceinline__ void mma16816(float& d0, float& d1, float& d2, float& d3,
                                         uint32_t a0, uint32_t a1, uint32_t a2, uint32_t a3,
                                         uint32_t b0, uint32_t b1) {
    asm volatile("mma.sync.aligned.m16n8k16.row.col.f32.bf16.bf16.f32 "
                 "{%0,%1,%2,%3},{%4,%5,%6,%7},{%8,%9},{%0,%1,%2,%3};"
                 : "+f"(d0), "+f"(d1), "+f"(d2), "+f"(d3)
                 : "r"(a0), "r"(a1), "r"(a2), "r"(a3), "r"(b0), "r"(b1));
}

// ---------------------------------------------------------------------------
// Kernel 1: merged prep — job y=0: pad border of g_xp; y=1: fused weight hi/lo
// ---------------------------------------------------------------------------
#define NBORD_ (2*WP_ + 2*(HP_-2))   // 772
__global__ void prep_kernel(const float* __restrict__ w) {
    int i = blockIdx.x * blockDim.x + threadIdx.x;
    int job = blockIdx.y;
    if (job == 0) {
        if (i >= B_ * NBORD_ * 16) return;
        int b   = i / (NBORD_ * 16);
        int r   = i % (NBORD_ * 16);
        int pix = r >> 4;
        int cq  = r & 15;
        int ph, pw;
        if (pix < WP_)            { ph = 0;        pw = pix; }
        else if (pix < 2*WP_)     { ph = HP_ - 1;  pw = pix - WP_; }
        else if (pix < 2*WP_ + (HP_-2)) { ph = pix - 2*WP_ + 1;  pw = 0; }
        else                      { ph = pix - (2*WP_ + (HP_-2)) + 1; pw = WP_ - 1; }
        reinterpret_cast<float4*>(g_xp + ((size_t)b * HPWP_ + ph * WP_ + pw) * C_)[cq] =
            make_float4(0.f, 0.f, 0.f, 0.f);
    } else {
        if (i >= KK_*C_*C_) return;
        int kk = i / (C_*C_);
        int oc = (i >> 6) & 63;
        int c  = i & 63;
        float v = w[oc * 576 + c * KK_ + kk];
        __nv_bfloat16 h = __float2bfloat16(v);
        float hf = __bfloat162float(h);
        __nv_bfloat16 l = __float2bfloat16(v - hf);
        uint16_t hb, lb;
        memcpy(&hb, &h, 2); memcpy(&lb, &l, 2);
        g_wtbh[(kk * C_ + oc) * C_ + c] = hb;
        g_wtbl[(kk * C_ + oc) * C_ + c] = lb;
    }
}

// ---------------------------------------------------------------------------
// Kernel 2: NCHW -> padded NHWC transpose (interior)
// ---------------------------------------------------------------------------
__global__ __launch_bounds__(256) void nhwc_kernel(const float* __restrict__ x) {
    __shared__ float tile[C_][33];
    const int tid = threadIdx.x;
    const int b   = blockIdx.y;
    const int pix0 = blockIdx.x * 32;

    {
        int ty = tid >> 5, tx = tid & 31;
        #pragma unroll
        for (int c0 = 0; c0 < C_; c0 += 8)
            tile[c0 + ty][tx] = x[((size_t)b * C_ + c0 + ty) * HW_ + pix0 + tx];
    }
    __syncthreads();
    {
        int pi = tid >> 6, c = tid & 63;
        #pragma unroll
        for (int j = 0; j < 8; ++j) {
            int pix = pix0 + j * 4 + pi;
            int ph = pix / W_ + 1, pw = pix % W_ + 1;
            g_xp[((size_t)b * HPWP_ + ph * WP_ + pw) * C_ + c] = tile[c][j * 4 + pi];
        }
    }
}

// ---------------------------------------------------------------------------
// Kernel 3: offset-predicting conv (R6 proven version).
// ---------------------------------------------------------------------------
#define WPITCH_ 12
__global__ __launch_bounds__(256) void offconv_kernel(
    const float* __restrict__ x, const float* __restrict__ depth,
    const float* __restrict__ w_off, const float* __restrict__ bias)
{
    __shared__ __align__(16) float w_s[CI_*KK_*WPITCH_];   // 28080 B
    const int tid = threadIdx.x;
    const int ocg = blockIdx.y;           // 0/1
    const int b   = blockIdx.z;
    const int ob  = ocg * OCH_;

    for (int i = tid; i < CI_*KK_*OCH_; i += 256) {
        int ct = i / OCH_, o = i % OCH_;
        w_s[ct * WPITCH_ + o] = w_off[(ob + o) * (CI_*KK_) + ct];
    }
    __syncthreads();

    const int p0 = blockIdx.x * 512 + tid;
    const int p1 = p0 + 256;

    int ti0[KK_], ti1[KK_];
    {
        int oh0 = p0 / W_, ow0 = p0 % W_;
        int oh1 = p1 / W_, ow1 = p1 % W_;
        #pragma unroll
        for (int t = 0; t < KK_; ++t) {
            int ky = t / 3 - 1, kx = t % 3 - 1;
            int ih0 = oh0 + ky, iw0 = ow0 + kx;
            int ih1 = oh1 + ky, iw1 = ow1 + kx;
            ti0[t] = (ih0 >= 0 && ih0 < H_ && iw0 >= 0 && iw0 < W_) ? ih0 * W_ + iw0 : -1;
            ti1[t] = (ih1 >= 0 && ih1 < H_ && iw1 >= 0 && iw1 < W_) ? ih1 * W_ + iw1 : -1;
        }
    }

    float acc0[OCH_], acc1[OCH_];
    #pragma unroll
    for (int o = 0; o < OCH_; ++o) { float bo = bias[ob + o]; acc0[o] = bo; acc1[o] = bo; }

    for (int c = 0; c < CI_; ++c) {
        const float* plane = (c < C_) ? (x + ((size_t)b * C_ + c) * HW_)
                                      : (depth + (size_t)b * HW_);
        float v0[KK_], v1[KK_];
        #pragma unroll
        for (int t = 0; t < KK_; ++t) {
            v0[t] = (ti0[t] >= 0) ? plane[ti0[t]] : 0.f;
            v1[t] = (ti1[t] >= 0) ? plane[ti1[t]] : 0.f;
        }
        #pragma unroll
        for (int t = 0; t < KK_; ++t) {
            const float* wp = &w_s[(c * KK_ + t) * WPITCH_];
            float4 wa = *reinterpret_cast<const float4*>(wp);
            float4 wb = *reinterpret_cast<const float4*>(wp + 4);
            float  wc = wp[8];
            acc0[0] = fmaf(v0[t], wa.x, acc0[0]);
            acc0[1] = fmaf(v0[t], wa.y, acc0[1]);
            acc0[2] = fmaf(v0[t], wa.z, acc0[2]);
            acc0[3] = fmaf(v0[t], wa.w, acc0[3]);
            acc0[4] = fmaf(v0[t], wb.x, acc0[4]);
            acc0[5] = fmaf(v0[t], wb.y, acc0[5]);
            acc0[6] = fmaf(v0[t], wb.z, acc0[6]);
            acc0[7] = fmaf(v0[t], wb.w, acc0[7]);
            acc0[8] = fmaf(v0[t], wc,   acc0[8]);
            acc1[0] = fmaf(v1[t], wa.x, acc1[0]);
            acc1[1] = fmaf(v1[t], wa.y, acc1[1]);
            acc1[2] = fmaf(v1[t], wa.z, acc1[2]);
            acc1[3] = fmaf(v1[t], wa.w, acc1[3]);
            acc1[4] = fmaf(v1[t], wb.x, acc1[4]);
            acc1[5] = fmaf(v1[t], wb.y, acc1[5]);
            acc1[6] = fmaf(v1[t], wb.z, acc1[6]);
            acc1[7] = fmaf(v1[t], wb.w, acc1[7]);
            acc1[8] = fmaf(v1[t], wc,   acc1[8]);
        }
    }

    #pragma unroll
    for (int o = 0; o < OCH_; ++o) {
        g_off[((size_t)b * OC_ + ob + o) * HW_ + p0] = acc0[o];
        g_off[((size_t)b * OC_ + ob + o) * HW_ + p1] = acc1[o];
    }
}

// ---------------------------------------------------------------------------
// Kernel 4: fused bilinear gather + mma.sync bf16 GEMM (3-term hi/lo split).
// Block: 128 px x 64 oc, 256 threads / 8 warps. Single-buffered A + staged B.
// Taps: single per-kk buffer, computed for kk+1 DURING the mma(kk) phase
// (no extra sync). smem 55.5 KB -> 4 blocks/SM = 32 warps (50% occ).
// ---------------------------------------------------------------------------
#define APITCH_ 72
#define MPX_    128
#define ATILE_  (MPX_ * APITCH_)            // 9216 uint16
#define BTILE_  (C_ * APITCH_)              // 4608 uint16
#define SM_AHI  0
#define SM_ALO  (ATILE_ * 2)                // 18432
#define SM_BHI  (SM_ALO + ATILE_ * 2)       // 36864
#define SM_BLO  (SM_BHI + BTILE_ * 2)       // 46080
#define SM_TIDX (SM_BLO + BTILE_ * 2)       // 55296
#define SM_TA   (SM_TIDX + MPX_ * 4)        // 55808
#define SM_TOT  (SM_TA + MPX_ * 8)          // 56832

struct __align__(8) TapA { float ax, ay; };

__global__ __launch_bounds__(256, 4) void fused_mma_kernel(float* __restrict__ out)
{
    extern __shared__ char sm[];
    uint16_t* Ahi = reinterpret_cast<uint16_t*>(sm + SM_AHI);   // [ATILE_]
    uint16_t* Alo = reinterpret_cast<uint16_t*>(sm + SM_ALO);   // [ATILE_]
    uint16_t* Bhi = reinterpret_cast<uint16_t*>(sm + SM_BHI);   // [BTILE_]
    uint16_t* Blo = reinterpret_cast<uint16_t*>(sm + SM_BLO);   // [BTILE_]
    int*  tap_idx = reinterpret_cast<int*>(sm + SM_TIDX);       // [MPX_]
    TapA* tap_a   = reinterpret_cast<TapA*>(sm + SM_TA);        // [MPX_]

    const int tid  = threadIdx.x;
    const int wid  = tid >> 5;
    const int lane = tid & 31;
    const int b    = blockIdx.y;
    const int pix0 = blockIdx.x * MPX_;

    const int ocg = wid & 1;    // 0/1: oc group (32 oc)
    const int pxg = wid >> 1;   // 0..3: pixel group (32 px)

    float acc[2][4][4];
    #pragma unroll
    for (int mi = 0; mi < 2; ++mi)
        #pragma unroll
        for (int ni = 0; ni < 4; ++ni)
            #pragma unroll
            for (int r = 0; r < 4; ++r) acc[mi][ni][r] = 0.f;

    const float* xb = g_xp + (size_t)b * HPWP_ * C_;
    const int cg = tid & 15;    // channel group (4 ch)
    const int pb = tid >> 4;    // 0..15

    // compute taps for one kk into the (single) tap buffer; tid<128 only
    auto taps = [&](int kk) {
        if (tid < MPX_) {
            int pix = pix0 + tid;
            int oh = pix / W_, ow = pix % W_;
            float ox = g_off[((size_t)b * OC_ + kk) * HW_ + pix];
            float oy = g_off[((size_t)b * OC_ + KK_ + kk) * HW_ + pix];
            float cx = (float)(oh + kk / 3) + ox;
            float cy = (float)(ow + kk % 3) + oy;
            cx = fminf(fmaxf(cx, 0.f), (float)(HP_ - 1));
            cy = fminf(fmaxf(cy, 0.f), (float)(WP_ - 1));
            int tlx = (int)floorf(cx); tlx = min(max(tlx, 0), HP_ - 2);
            int tly = (int)floorf(cy); tly = min(max(tly, 0), WP_ - 2);
            tap_idx[tid] = tlx * WP_ + tly;
            tap_a[tid].ax = cx - (float)tlx;
            tap_a[tid].ay = cy - (float)tly;
        }
    };

    auto gather = [&]() {
        #pragma unroll 2
        for (int i = 0; i < 8; ++i) {
            int p = pb + 16 * i;
            int idx = tap_idx[p];
            TapA a = tap_a[p];
            const float4* q = reinterpret_cast<const float4*>(xb + (size_t)idx * C_) + cg;
            float4 x00 = q[0];
            float4 x01 = q[16];
            float4 x10 = q[WP_ * 16];
            float4 x11 = q[(WP_ + 1) * 16];
            float4 v;
            {
                float r0, r1;
                r0 = fmaf(a.ay, x01.x - x00.x, x00.x);
                r1 = fmaf(a.ay, x11.x - x10.x, x10.x);
                v.x = fmaf(a.ax, r1 - r0, r0);
                r0 = fmaf(a.ay, x01.y - x00.y, x00.y);
                r1 = fmaf(a.ay, x11.y - x10.y, x10.y);
                v.y = fmaf(a.ax, r1 - r0, r0);
                r0 = fmaf(a.ay, x01.z - x00.z, x00.z);
                r1 = fmaf(a.ay, x11.z - x10.z, x10.z);
                v.z = fmaf(a.ax, r1 - r0, r0);
                r0 = fmaf(a.ay, x01.w - x00.w, x00.w);
                r1 = fmaf(a.ay, x11.w - x10.w, x10.w);
                v.w = fmaf(a.ax, r1 - r0, r0);
            }
            uint32_t h01 = cvt_bf16x2(v.y, v.x);
            uint32_t h23 = cvt_bf16x2(v.w, v.z);
            float l0 = v.x - __uint_as_float(h01 << 16);
            float l1 = v.y - __uint_as_float(h01 & 0xFFFF0000u);
            float l2 = v.z - __uint_as_float(h23 << 16);
            float l3 = v.w - __uint_as_float(h23 & 0xFFFF0000u);
            uint32_t q01 = cvt_bf16x2(l1, l0);
            uint32_t q23 = cvt_bf16x2(l3, l2);
            int eo = p * APITCH_ + cg * 4;
            *reinterpret_cast<uint2*>(&Ahi[eo]) = make_uint2(h01, h23);
            *reinterpret_cast<uint2*>(&Alo[eo]) = make_uint2(q01, q23);
        }
    };

    // stage B chunk kk into smem (coalesced uint2 copy, pitch 72)
    auto stageB = [&](int kk) {
        const uint2* sh = reinterpret_cast<const uint2*>(g_wtbh + kk * (C_*C_));
        const uint2* sl = reinterpret_cast<const uint2*>(g_wtbl + kk * (C_*C_));
        #pragma unroll
        for (int e = tid; e < 1024; e += 256) {
            int oc = e >> 4, c4 = e & 15;
            int doff = oc * APITCH_ + c4 * 4;
            *reinterpret_cast<uint2*>(&Bhi[doff]) = sh[e];
            *reinterpret_cast<uint2*>(&Blo[doff]) = sl[e];
        }
    };

    taps(0);
    __syncthreads();            // taps(0) visible
    gather();
    stageB(0);
    __syncthreads();            // A(0)/B(0) visible

    const int arow = pxg * 32 + (lane >> 2);
    const int akol = (lane & 3) * 2;
    const int brow = ocg * 32 + (lane >> 2);

    for (int kk = 0; kk < KK_; ++kk) {
        // taps for kk+1: written during the mma phase; tap buffer is idle here
        if (kk + 1 < KK_) taps(kk + 1);

        #pragma unroll
        for (int ki = 0; ki < 4; ++ki) {
            const int k0 = ki * 16 + akol;
            uint32_t ah[2][4], al[2][4];
            #pragma unroll
            for (int mi = 0; mi < 2; ++mi) {
                int r0 = (arow + mi * 16) * APITCH_ + k0;
                int r1 = r0 + 8 * APITCH_;
                ah[mi][0] = *reinterpret_cast<const uint32_t*>(&Ahi[r0]);
                ah[mi][1] = *reinterpret_cast<const uint32_t*>(&Ahi[r1]);
                ah[mi][2] = *reinterpret_cast<const uint32_t*>(&Ahi[r0 + 8]);
                ah[mi][3] = *reinterpret_cast<const uint32_t*>(&Ahi[r1 + 8]);
                al[mi][0] = *reinterpret_cast<const uint32_t*>(&Alo[r0]);
                al[mi][1] = *reinterpret_cast<const uint32_t*>(&Alo[r1]);
                al[mi][2] = *reinterpret_cast<const uint32_t*>(&Alo[r0 + 8]);
                al[mi][3] = *reinterpret_cast<const uint32_t*>(&Alo[r1 + 8]);
            }
            #pragma unroll
            for (int ni = 0; ni < 4; ++ni) {
                int boff = (brow + ni * 8) * APITCH_ + k0;
                uint32_t bh0 = *reinterpret_cast<const uint32_t*>(&Bhi[boff]);
                uint32_t bh1 = *reinterpret_cast<const uint32_t*>(&Bhi[boff + 8]);
                uint32_t bl0 = *reinterpret_cast<const uint32_t*>(&Blo[boff]);
                uint32_t bl1 = *reinterpret_cast<const uint32_t*>(&Blo[boff + 8]);
                #pragma unroll
                for (int mi = 0; mi < 2; ++mi) {
                    float* d = acc[mi][ni];
                    mma16816(d[0], d[1], d[2], d[3],
                             ah[mi][0], ah[mi][1], ah[mi][2], ah[mi][3], bh0, bh1);
                    mma16816(d[0], d[1], d[2], d[3],
                             al[mi][0], al[mi][1], al[mi][2], al[mi][3], bh0, bh1);
                    mma16816(d[0], d[1], d[2], d[3],
                             ah[mi][0], ah[mi][1], ah[mi][2], ah[mi][3], bl0, bl1);
                }
            }
        }
        if (kk + 1 < KK_) {
            __syncthreads();           // mma(kk) done, taps(kk+1) visible
            gather();
            stageB(kk + 1);
            __syncthreads();           // A/B(kk+1) visible
        }
    }

    // --- epilogue: D fragment -> out[b][oc][pix] ---
    #pragma unroll
    for (int mi = 0; mi < 2; ++mi) {
        int px = pix0 + pxg * 32 + mi * 16 + (lane >> 2);
        #pragma unroll
        for (int ni = 0; ni < 4; ++ni) {
            int oc = ocg * 32 + ni * 8 + (lane & 3) * 2;
            float* o0 = out + ((size_t)b * C_ + oc) * HW_;
            float* o1 = out + ((size_t)b * C_ + oc + 1) * HW_;
            o0[px]     = acc[mi][ni][0];
            o1[px]     = acc[mi][ni][1];
            o0[px + 8] = acc[mi][ni][2];
            o1[px + 8] = acc[mi][ni][3];
        }
    }
}

// ---------------------------------------------------------------------------
// Launch
// ---------------------------------------------------------------------------
extern "C" void kernel_launch(void* const* d_in, const int* in_sizes, int n_in,
                              void* d_out, int out_size) {
    const float* x      = (const float*)d_in[0];
    const float* depth  = (const float*)d_in[1];
    const float* w_off  = (const float*)d_in[2];
    const float* bias   = (const float*)d_in[3];
    const float* weight = (const float*)d_in[4];
    float* out = (float*)d_out;

    {
        dim3 grid(144, 2);
        prep_kernel<<<grid, 256>>>(weight);
    }
    {
        dim3 grid(HW_ / 32, B_);
        nhwc_kernel<<<grid, 256>>>(x);
    }
    {
        dim3 grid(HW_ / 512, 2, B_);
        offconv_kernel<<<grid, 256>>>(x, depth, w_off, bias);
    }
    {
        static bool attr_set = false;
        if (!attr_set) {
            cudaFuncSetAttribute(fused_mma_kernel,
                                 cudaFuncAttributeMaxDynamicSharedMemorySize, SM_TOT);
            attr_set = true;
        }
        dim3 grid(HW_ / MPX_, B_);
        fused_mma_kernel<<<grid, 256, SM_TOT>>>(out);
    }
}

// round 13
// speedup vs baseline: 3.4254x; 1.1100x over previous
#include <cuda_runtime.h>
#include <cuda_bf16.h>
#include <cstdint>
#include <cstring>

// Problem constants
#define B_   2
#define C_   64
#define H_   192
#define W_   192
#define HW_  (H_*W_)          // 36864
#define KK_  9
#define HP_  194
#define WP_  194
#define HPWP_ (HP_*WP_)       // 37636
#define CI_  65               // C+1
#define OC_  18               // 2*KK

// Scratch (device globals)
__device__ float    g_xp  [B_*HPWP_*C_];     // padded x, NHWC  (~19.3 MB)
__device__ float    g_dp  [B_*HPWP_];        // padded depth (~0.3 MB)
__device__ float    g_off [B_*OC_*HW_];      // offsets (~5.3 MB)
__device__ uint16_t g_wtbh[KK_*C_*C_];       // fused weight hi bf16, [kk][oc][c]
__device__ uint16_t g_wtbl[KK_*C_*C_];       // fused weight lo bf16
__device__ uint16_t g_wobh[10*32*C_];        // offconv weight hi bf16, [chunk][oc32][c64]
__device__ uint16_t g_wobl[10*32*C_];        // offconv weight lo bf16

// ---------------------------------------------------------------------------
// helpers
// ---------------------------------------------------------------------------
__device__ __forceinline__ uint32_t cvt_bf16x2(float hi, float lo) {
    uint32_t r;
    asm("cvt.rn.satfinite.bf16x2.f32 %0, %1, %2;" : "=r"(r) : "f"(hi), "f"(lo));
    return r;
}

__device__ __forceinline__ void mma16816(float& d0, float& d1, float& d2, float& d3,
                                         uint32_t a0, uint32_t a1, uint32_t a2, uint32_t a3,
                                         uint32_t b0, uint32_t b1) {
    asm volatile("mma.sync.aligned.m16n8k16.row.col.f32.bf16.bf16.f32 "
                 "{%0,%1,%2,%3},{%4,%5,%6,%7},{%8,%9},{%0,%1,%2,%3};"
                 : "+f"(d0), "+f"(d1), "+f"(d2), "+f"(d3)
                 : "r"(a0), "r"(a1), "r"(a2), "r"(a3), "r"(b0), "r"(b1));
}

__device__ __forceinline__ void bf16_split(float v, uint16_t& h, uint16_t& l) {
    __nv_bfloat16 hb = __float2bfloat16(v);
    float hf = __bfloat162float(hb);
    __nv_bfloat16 lb = __float2bfloat16(v - hf);
    memcpy(&h, &hb, 2); memcpy(&l, &lb, 2);
}

// split a float4 into hi/lo bf16x2 pairs and store to pitch-72 smem
__device__ __forceinline__ void split_store(uint16_t* Ahi, uint16_t* Alo,
                                            int eo, float4 v) {
    uint32_t h01 = cvt_bf16x2(v.y, v.x);
    uint32_t h23 = cvt_bf16x2(v.w, v.z);
    float l0 = v.x - __uint_as_float(h01 << 16);
    float l1 = v.y - __uint_as_float(h01 & 0xFFFF0000u);
    float l2 = v.z - __uint_as_float(h23 << 16);
    float l3 = v.w - __uint_as_float(h23 & 0xFFFF0000u);
    uint32_t q01 = cvt_bf16x2(l1, l0);
    uint32_t q23 = cvt_bf16x2(l3, l2);
    *reinterpret_cast<uint2*>(&Ahi[eo]) = make_uint2(h01, h23);
    *reinterpret_cast<uint2*>(&Alo[eo]) = make_uint2(q01, q23);
}

// ---------------------------------------------------------------------------
// Kernel 1: merged prep.
// job 0: zero border of g_xp; job 1: fused weights bf16 hi/lo;
// job 2: offconv GEMM weights [10][32][64]; job 3: padded depth plane.
// ---------------------------------------------------------------------------
#define NBORD_ (2*WP_ + 2*(HP_-2))   // 772
__global__ void prep_kernel(const float* __restrict__ w,
                            const float* __restrict__ w_off,
                            const float* __restrict__ depth) {
    int i = blockIdx.x * blockDim.x + threadIdx.x;
    int job = blockIdx.y;
    if (job == 0) {
        if (i >= B_ * NBORD_ * 16) return;
        int b   = i / (NBORD_ * 16);
        int r   = i % (NBORD_ * 16);
        int pix = r >> 4;
        int cq  = r & 15;
        int ph, pw;
        if (pix < WP_)            { ph = 0;        pw = pix; }
        else if (pix < 2*WP_)     { ph = HP_ - 1;  pw = pix - WP_; }
        else if (pix < 2*WP_ + (HP_-2)) { ph = pix - 2*WP_ + 1;  pw = 0; }
        else                      { ph = pix - (2*WP_ + (HP_-2)) + 1; pw = WP_ - 1; }
        reinterpret_cast<float4*>(g_xp + ((size_t)b * HPWP_ + ph * WP_ + pw) * C_)[cq] =
            make_float4(0.f, 0.f, 0.f, 0.f);
    } else if (job == 1) {
        if (i >= KK_*C_*C_) return;
        int kk = i / (C_*C_);
        int oc = (i >> 6) & 63;
        int c  = i & 63;
        float v = w[oc * 576 + c * KK_ + kk];
        uint16_t hb, lb; bf16_split(v, hb, lb);
        g_wtbh[(kk * C_ + oc) * C_ + c] = hb;
        g_wtbl[(kk * C_ + oc) * C_ + c] = lb;
    } else if (job == 2) {
        if (i >= 10*32*C_) return;
        int ch = i / (32*C_);
        int r  = i % (32*C_);
        int oc = r >> 6;
        int k  = r & 63;
        float v = 0.f;
        if (oc < OC_) {
            if (ch < 9)        v = w_off[(oc * CI_ + k) * KK_ + ch];   // x channel k, tap ch
            else if (k < KK_)  v = w_off[(oc * CI_ + 64) * KK_ + k];   // depth, tap k
        }
        uint16_t hb, lb; bf16_split(v, hb, lb);
        g_wobh[i] = hb;
        g_wobl[i] = lb;
    } else {
        if (i >= B_ * HPWP_) return;
        int b  = i / HPWP_;
        int pp = i % HPWP_;
        int ph = pp / WP_, pw = pp % WP_;
        float v = 0.f;
        if (ph >= 1 && ph <= H_ && pw >= 1 && pw <= W_)
            v = depth[(size_t)b * HW_ + (ph - 1) * W_ + (pw - 1)];
        g_dp[i] = v;
    }
}

// ---------------------------------------------------------------------------
// Kernel 2: NCHW -> padded NHWC transpose (interior)
// ---------------------------------------------------------------------------
__global__ __launch_bounds__(256) void nhwc_kernel(const float* __restrict__ x) {
    __shared__ float tile[C_][33];
    const int tid = threadIdx.x;
    const int b   = blockIdx.y;
    const int pix0 = blockIdx.x * 32;

    {
        int ty = tid >> 5, tx = tid & 31;
        #pragma unroll
        for (int c0 = 0; c0 < C_; c0 += 8)
            tile[c0 + ty][tx] = x[((size_t)b * C_ + c0 + ty) * HW_ + pix0 + tx];
    }
    __syncthreads();
    {
        int pi = tid >> 6, c = tid & 63;
        #pragma unroll
        for (int j = 0; j < 8; ++j) {
            int pix = pix0 + j * 4 + pi;
            int ph = pix / W_ + 1, pw = pix % W_ + 1;
            g_xp[((size_t)b * HPWP_ + ph * WP_ + pw) * C_ + c] = tile[c][j * 4 + pi];
        }
    }
}

// ---------------------------------------------------------------------------
// Kernel 3: offconv as mma.sync GEMM from padded NHWC x.
// Block: 128 px (M) x 32 oc (N, 18 used), 256 threads / 8 warps
// (warp w owns px rows w*16..w*16+15, all 32 oc).
// K: chunks 0..8 = x channels for tap ch (A row px, col c = xp row — coalesced
// 256B loads, no predication); chunk 9 = depth taps (ki=0 only).
// A/B staged in smem pitch 72; static smem 45 KB -> 4 blocks/SM.
// ---------------------------------------------------------------------------
#define APITCH_ 72

__global__ __launch_bounds__(256) void offmma_kernel(const float* __restrict__ bias)
{
    __shared__ __align__(16) uint16_t Ahi[128 * APITCH_];  // 18432 B
    __shared__ __align__(16) uint16_t Alo[128 * APITCH_];  // 18432 B
    __shared__ __align__(16) uint16_t Bhi[32 * APITCH_];   //  4608 B
    __shared__ __align__(16) uint16_t Blo[32 * APITCH_];   //  4608 B

    const int tid  = threadIdx.x;
    const int wid  = tid >> 5;
    const int lane = tid & 31;
    const int b    = blockIdx.y;
    const int pix0 = blockIdx.x * 128;

    const float* xb = g_xp + (size_t)b * HPWP_ * C_;
    const float* db = g_dp + (size_t)b * HPWP_;
    const int cg = tid & 15;    // channel group (4 ch)
    const int pb = tid >> 4;    // 0..15

    // fill A for chunk ch (x taps, or depth for ch==9)
    auto fillA = [&](int ch) {
        if (ch < 9) {
            const int dy = ch / 3, dx = ch % 3;   // padded-frame tap base
            #pragma unroll 2
            for (int i = 0; i < 8; ++i) {
                int p = pb + 16 * i;
                int pix = pix0 + p;
                int oh = pix / W_, ow = pix % W_;
                int idx = (oh + dy) * WP_ + (ow + dx);
                const float4* q = reinterpret_cast<const float4*>(xb + (size_t)idx * C_) + cg;
                split_store(Ahi, Alo, p * APITCH_ + cg * 4, q[0]);
            }
        } else {
            if (cg >= 4) return;                  // only cols 0..15 read (ki=0)
            #pragma unroll 2
            for (int i = 0; i < 8; ++i) {
                int p = pb + 16 * i;
                int pix = pix0 + p;
                int oh = pix / W_, ow = pix % W_;
                float4 v = make_float4(0.f, 0.f, 0.f, 0.f);
                float* ve = &v.x;
                #pragma unroll
                for (int e = 0; e < 4; ++e) {
                    int t = cg * 4 + e;
                    if (t < KK_)
                        ve[e] = db[(oh + t / 3) * WP_ + (ow + t % 3)];
                }
                split_store(Ahi, Alo, p * APITCH_ + cg * 4, v);
            }
        }
    };

    // stage B chunk into smem (coalesced uint2 copy, pitch 72)
    auto stageB = [&](int ch) {
        const uint2* sh = reinterpret_cast<const uint2*>(g_wobh + ch * (32*C_));
        const uint2* sl = reinterpret_cast<const uint2*>(g_wobl + ch * (32*C_));
        #pragma unroll
        for (int e = tid; e < 512; e += 256) {
            int oc = e >> 4, c4 = e & 15;
            int doff = oc * APITCH_ + c4 * 4;
            *reinterpret_cast<uint2*>(&Bhi[doff]) = sh[e];
            *reinterpret_cast<uint2*>(&Blo[doff]) = sl[e];
        }
    };

    float acc[4][4];
    #pragma unroll
    for (int ni = 0; ni < 4; ++ni)
        #pragma unroll
        for (int r = 0; r < 4; ++r) acc[ni][r] = 0.f;

    const int arow = wid * 16 + (lane >> 2);
    const int akol = (lane & 3) * 2;
    const int brow = lane >> 2;

    fillA(0);
    stageB(0);
    __syncthreads();

    for (int ch = 0; ch < 10; ++ch) {
        const int nki = (ch == 9) ? 1 : 4;
        for (int ki = 0; ki < nki; ++ki) {
            const int k0 = ki * 16 + akol;
            const int r0 = arow * APITCH_ + k0;
            const int r1 = r0 + 8 * APITCH_;
            uint32_t a0h = *reinterpret_cast<const uint32_t*>(&Ahi[r0]);
            uint32_t a1h = *reinterpret_cast<const uint32_t*>(&Ahi[r1]);
            uint32_t a2h = *reinterpret_cast<const uint32_t*>(&Ahi[r0 + 8]);
            uint32_t a3h = *reinterpret_cast<const uint32_t*>(&Ahi[r1 + 8]);
            uint32_t a0l = *reinterpret_cast<const uint32_t*>(&Alo[r0]);
            uint32_t a1l = *reinterpret_cast<const uint32_t*>(&Alo[r1]);
            uint32_t a2l = *reinterpret_cast<const uint32_t*>(&Alo[r0 + 8]);
            uint32_t a3l = *reinterpret_cast<const uint32_t*>(&Alo[r1 + 8]);
            #pragma unroll
            for (int ni = 0; ni < 4; ++ni) {
                int boff = (brow + ni * 8) * APITCH_ + k0;
                uint32_t bh0 = *reinterpret_cast<const uint32_t*>(&Bhi[boff]);
                uint32_t bh1 = *reinterpret_cast<const uint32_t*>(&Bhi[boff + 8]);
                uint32_t bl0 = *reinterpret_cast<const uint32_t*>(&Blo[boff]);
                uint32_t bl1 = *reinterpret_cast<const uint32_t*>(&Blo[boff + 8]);
                float* d = acc[ni];
                mma16816(d[0], d[1], d[2], d[3], a0h, a1h, a2h, a3h, bh0, bh1);
                mma16816(d[0], d[1], d[2], d[3], a0l, a1l, a2l, a3l, bh0, bh1);
                mma16816(d[0], d[1], d[2], d[3], a0h, a1h, a2h, a3h, bl0, bl1);
            }
        }
        if (ch + 1 < 10) {
            __syncthreads();
            fillA(ch + 1);
            stageB(ch + 1);
            __syncthreads();
        }
    }

    // epilogue: [16px][32oc] per warp -> g_off[b][oc][px] (+bias), oc<18 only
    const int px = pix0 + wid * 16 + (lane >> 2);
    #pragma unroll
    for (int ni = 0; ni < 3; ++ni) {            // ni=3 -> oc>=24, unused
        int oc = ni * 8 + (lane & 3) * 2;
        if (oc < OC_) {
            float b0 = bias[oc], b1 = bias[oc + 1];
            float* o0 = g_off + ((size_t)b * OC_ + oc) * HW_;
            float* o1 = g_off + ((size_t)b * OC_ + oc + 1) * HW_;
            o0[px]     = acc[ni][0] + b0;
            o1[px]     = acc[ni][1] + b1;
            o0[px + 8] = acc[ni][2] + b0;
            o1[px + 8] = acc[ni][3] + b1;
        }
    }
}

// ---------------------------------------------------------------------------
// Kernel 4: fused bilinear gather + mma.sync bf16 GEMM (unchanged from R11)
// ---------------------------------------------------------------------------
#define MPX_    128
#define ATILE_  (MPX_ * APITCH_)            // 9216 uint16
#define BTILE_  (C_ * APITCH_)              // 4608 uint16
#define SM_AHI  0
#define SM_ALO  (ATILE_ * 2)                // 18432
#define SM_BHI  (SM_ALO + ATILE_ * 2)       // 36864
#define SM_BLO  (SM_BHI + BTILE_ * 2)       // 46080
#define SM_TIDX (SM_BLO + BTILE_ * 2)       // 55296
#define SM_TA   (SM_TIDX + MPX_ * 4)        // 55808
#define SM_TOT  (SM_TA + MPX_ * 8)          // 56832

struct __align__(8) TapA { float ax, ay; };

__global__ __launch_bounds__(256, 4) void fused_mma_kernel(float* __restrict__ out)
{
    extern __shared__ char sm[];
    uint16_t* Ahi = reinterpret_cast<uint16_t*>(sm + SM_AHI);
    uint16_t* Alo = reinterpret_cast<uint16_t*>(sm + SM_ALO);
    uint16_t* Bhi = reinterpret_cast<uint16_t*>(sm + SM_BHI);
    uint16_t* Blo = reinterpret_cast<uint16_t*>(sm + SM_BLO);
    int*  tap_idx = reinterpret_cast<int*>(sm + SM_TIDX);
    TapA* tap_a   = reinterpret_cast<TapA*>(sm + SM_TA);

    const int tid  = threadIdx.x;
    const int wid  = tid >> 5;
    const int lane = tid & 31;
    const int b    = blockIdx.y;
    const int pix0 = blockIdx.x * MPX_;

    const int ocg = wid & 1;
    const int pxg = wid >> 1;

    float acc[2][4][4];
    #pragma unroll
    for (int mi = 0; mi < 2; ++mi)
        #pragma unroll
        for (int ni = 0; ni < 4; ++ni)
            #pragma unroll
            for (int r = 0; r < 4; ++r) acc[mi][ni][r] = 0.f;

    const float* xb = g_xp + (size_t)b * HPWP_ * C_;
    const int cg = tid & 15;
    const int pb = tid >> 4;

    auto taps = [&](int kk) {
        if (tid < MPX_) {
            int pix = pix0 + tid;
            int oh = pix / W_, ow = pix % W_;
            float ox = g_off[((size_t)b * OC_ + kk) * HW_ + pix];
            float oy = g_off[((size_t)b * OC_ + KK_ + kk) * HW_ + pix];
            float cx = (float)(oh + kk / 3) + ox;
            float cy = (float)(ow + kk % 3) + oy;
            cx = fminf(fmaxf(cx, 0.f), (float)(HP_ - 1));
            cy = fminf(fmaxf(cy, 0.f), (float)(WP_ - 1));
            int tlx = (int)floorf(cx); tlx = min(max(tlx, 0), HP_ - 2);
            int tly = (int)floorf(cy); tly = min(max(tly, 0), WP_ - 2);
            tap_idx[tid] = tlx * WP_ + tly;
            tap_a[tid].ax = cx - (float)tlx;
            tap_a[tid].ay = cy - (float)tly;
        }
    };

    auto gather = [&]() {
        #pragma unroll 2
        for (int i = 0; i < 8; ++i) {
            int p = pb + 16 * i;
            int idx = tap_idx[p];
            TapA a = tap_a[p];
            const float4* q = reinterpret_cast<const float4*>(xb + (size_t)idx * C_) + cg;
            float4 x00 = q[0];
            float4 x01 = q[16];
            float4 x10 = q[WP_ * 16];
            float4 x11 = q[(WP_ + 1) * 16];
            float4 v;
            {
                float r0, r1;
                r0 = fmaf(a.ay, x01.x - x00.x, x00.x);
                r1 = fmaf(a.ay, x11.x - x10.x, x10.x);
                v.x = fmaf(a.ax, r1 - r0, r0);
                r0 = fmaf(a.ay, x01.y - x00.y, x00.y);
                r1 = fmaf(a.ay, x11.y - x10.y, x10.y);
                v.y = fmaf(a.ax, r1 - r0, r0);
                r0 = fmaf(a.ay, x01.z - x00.z, x00.z);
                r1 = fmaf(a.ay, x11.z - x10.z, x10.z);
                v.z = fmaf(a.ax, r1 - r0, r0);
                r0 = fmaf(a.ay, x01.w - x00.w, x00.w);
                r1 = fmaf(a.ay, x11.w - x10.w, x10.w);
                v.w = fmaf(a.ax, r1 - r0, r0);
            }
            split_store(Ahi, Alo, p * APITCH_ + cg * 4, v);
        }
    };

    auto stageB = [&](int kk) {
        const uint2* sh = reinterpret_cast<const uint2*>(g_wtbh + kk * (C_*C_));
        const uint2* sl = reinterpret_cast<const uint2*>(g_wtbl + kk * (C_*C_));
        #pragma unroll
        for (int e = tid; e < 1024; e += 256) {
            int oc = e >> 4, c4 = e & 15;
            int doff = oc * APITCH_ + c4 * 4;
            *reinterpret_cast<uint2*>(&Bhi[doff]) = sh[e];
            *reinterpret_cast<uint2*>(&Blo[doff]) = sl[e];
        }
    };

    taps(0);
    __syncthreads();
    gather();
    stageB(0);
    __syncthreads();

    const int arow = pxg * 32 + (lane >> 2);
    const int akol = (lane & 3) * 2;
    const int brow = ocg * 32 + (lane >> 2);

    for (int kk = 0; kk < KK_; ++kk) {
        if (kk + 1 < KK_) taps(kk + 1);

        #pragma unroll
        for (int ki = 0; ki < 4; ++ki) {
            const int k0 = ki * 16 + akol;
            uint32_t ah[2][4], al[2][4];
            #pragma unroll
            for (int mi = 0; mi < 2; ++mi) {
                int r0 = (arow + mi * 16) * APITCH_ + k0;
                int r1 = r0 + 8 * APITCH_;
                ah[mi][0] = *reinterpret_cast<const uint32_t*>(&Ahi[r0]);
                ah[mi][1] = *reinterpret_cast<const uint32_t*>(&Ahi[r1]);
                ah[mi][2] = *reinterpret_cast<const uint32_t*>(&Ahi[r0 + 8]);
                ah[mi][3] = *reinterpret_cast<const uint32_t*>(&Ahi[r1 + 8]);
                al[mi][0] = *reinterpret_cast<const uint32_t*>(&Alo[r0]);
                al[mi][1] = *reinterpret_cast<const uint32_t*>(&Alo[r1]);
                al[mi][2] = *reinterpret_cast<const uint32_t*>(&Alo[r0 + 8]);
                al[mi][3] = *reinterpret_cast<const uint32_t*>(&Alo[r1 + 8]);
            }
            #pragma unroll
            for (int ni = 0; ni < 4; ++ni) {
                int boff = (brow + ni * 8) * APITCH_ + k0;
                uint32_t bh0 = *reinterpret_cast<const uint32_t*>(&Bhi[boff]);
                uint32_t bh1 = *reinterpret_cast<const uint32_t*>(&Bhi[boff + 8]);
                uint32_t bl0 = *reinterpret_cast<const uint32_t*>(&Blo[boff]);
                uint32_t bl1 = *reinterpret_cast<const uint32_t*>(&Blo[boff + 8]);
                #pragma unroll
                for (int mi = 0; mi < 2; ++mi) {
                    float* d = acc[mi][ni];
                    mma16816(d[0], d[1], d[2], d[3],
                             ah[mi][0], ah[mi][1], ah[mi][2], ah[mi][3], bh0, bh1);
                    mma16816(d[0], d[1], d[2], d[3],
                             al[mi][0], al[mi][1], al[mi][2], al[mi][3], bh0, bh1);
                    mma16816(d[0], d[1], d[2], d[3],
                             ah[mi][0], ah[mi][1], ah[mi][2], ah[mi][3], bl0, bl1);
                }
            }
        }
        if (kk + 1 < KK_) {
            __syncthreads();
            gather();
            stageB(kk + 1);
            __syncthreads();
        }
    }

    #pragma unroll
    for (int mi = 0; mi < 2; ++mi) {
        int px = pix0 + pxg * 32 + mi * 16 + (lane >> 2);
        #pragma unroll
        for (int ni = 0; ni < 4; ++ni) {
            int oc = ocg * 32 + ni * 8 + (lane & 3) * 2;
            float* o0 = out + ((size_t)b * C_ + oc) * HW_;
            float* o1 = out + ((size_t)b * C_ + oc + 1) * HW_;
            o0[px]     = acc[mi][ni][0];
            o1[px]     = acc[mi][ni][1];
            o0[px + 8] = acc[mi][ni][2];
            o1[px + 8] = acc[mi][ni][3];
        }
    }
}

// ---------------------------------------------------------------------------
// Launch
// ---------------------------------------------------------------------------
extern "C" void kernel_launch(void* const* d_in, const int* in_sizes, int n_in,
                              void* d_out, int out_size) {
    const float* x      = (const float*)d_in[0];
    const float* depth  = (const float*)d_in[1];
    const float* w_off  = (const float*)d_in[2];
    const float* bias   = (const float*)d_in[3];
    const float* weight = (const float*)d_in[4];
    float* out = (float*)d_out;

    {
        dim3 grid(295, 4);   // 295*256 = 75520 >= all job sizes
        prep_kernel<<<grid, 256>>>(weight, w_off, depth);
    }
    {
        dim3 grid(HW_ / 32, B_);
        nhwc_kernel<<<grid, 256>>>(x);
    }
    {
        dim3 grid(HW_ / 128, B_);
        offmma_kernel<<<grid, 256>>>(bias);
    }
    {
        static bool attr_set = false;
        if (!attr_set) {
            cudaFuncSetAttribute(fused_mma_kernel,
                                 cudaFuncAttributeMaxDynamicSharedMemorySize, SM_TOT);
            attr_set = true;
        }
        dim3 grid(HW_ / MPX_, B_);
        fused_mma_kernel<<<grid, 256, SM_TOT>>>(out);
    }
}

// round 14
// speedup vs baseline: 3.4759x; 1.0147x over previous
#include <cuda_runtime.h>
#include <cuda_bf16.h>
#include <cuda_fp16.h>
#include <cstdint>
#include <cstring>

// Problem constants
#define B_   2
#define C_   64
#define H_   192
#define W_   192
#define HW_  (H_*W_)          // 36864
#define KK_  9
#define HP_  194
#define WP_  194
#define HPWP_ (HP_*WP_)       // 37636
#define CI_  65               // C+1
#define OC_  18               // 2*KK

// Scratch (device globals)
__device__ __half   g_xp  [B_*HPWP_*C_];     // padded x, NHWC fp16 (~9.6 MB)
__device__ float    g_dp  [B_*HPWP_];        // padded depth (~0.3 MB)
__device__ float    g_off [B_*OC_*HW_];      // offsets (~5.3 MB)
__device__ uint16_t g_wtbh[KK_*C_*C_];       // fused weight hi bf16, [kk][oc][c]
__device__ uint16_t g_wtbl[KK_*C_*C_];       // fused weight lo bf16
__device__ uint16_t g_wobh[10*32*C_];        // offconv weight hi bf16, [chunk][oc32][c64]
__device__ uint16_t g_wobl[10*32*C_];        // offconv weight lo bf16

// ---------------------------------------------------------------------------
// helpers
// ---------------------------------------------------------------------------
__device__ __forceinline__ uint32_t cvt_bf16x2(float hi, float lo) {
    uint32_t r;
    asm("cvt.rn.satfinite.bf16x2.f32 %0, %1, %2;" : "=r"(r) : "f"(hi), "f"(lo));
    return r;
}

__device__ __forceinline__ float4 h4_to_f4(uint2 u) {
    __half2 h0 = *reinterpret_cast<__half2*>(&u.x);
    __half2 h1 = *reinterpret_cast<__half2*>(&u.y);
    float2 f0 = __half22float2(h0);
    float2 f1 = __half22float2(h1);
    return make_float4(f0.x, f0.y, f1.x, f1.y);
}

__device__ __forceinline__ void mma16816(float& d0, float& d1, float& d2, float& d3,
                                         uint32_t a0, uint32_t a1, uint32_t a2, uint32_t a3,
                                         uint32_t b0, uint32_t b1) {
    asm volatile("mma.sync.aligned.m16n8k16.row.col.f32.bf16.bf16.f32 "
                 "{%0,%1,%2,%3},{%4,%5,%6,%7},{%8,%9},{%0,%1,%2,%3};"
                 : "+f"(d0), "+f"(d1), "+f"(d2), "+f"(d3)
                 : "r"(a0), "r"(a1), "r"(a2), "r"(a3), "r"(b0), "r"(b1));
}

__device__ __forceinline__ void bf16_split(float v, uint16_t& h, uint16_t& l) {
    __nv_bfloat16 hb = __float2bfloat16(v);
    float hf = __bfloat162float(hb);
    __nv_bfloat16 lb = __float2bfloat16(v - hf);
    memcpy(&h, &hb, 2); memcpy(&l, &lb, 2);
}

// split a float4 into hi/lo bf16x2 pairs and store to pitch-72 smem
__device__ __forceinline__ void split_store(uint16_t* Ahi, uint16_t* Alo,
                                            int eo, float4 v) {
    uint32_t h01 = cvt_bf16x2(v.y, v.x);
    uint32_t h23 = cvt_bf16x2(v.w, v.z);
    float l0 = v.x - __uint_as_float(h01 << 16);
    float l1 = v.y - __uint_as_float(h01 & 0xFFFF0000u);
    float l2 = v.z - __uint_as_float(h23 << 16);
    float l3 = v.w - __uint_as_float(h23 & 0xFFFF0000u);
    uint32_t q01 = cvt_bf16x2(l1, l0);
    uint32_t q23 = cvt_bf16x2(l3, l2);
    *reinterpret_cast<uint2*>(&Ahi[eo]) = make_uint2(h01, h23);
    *reinterpret_cast<uint2*>(&Alo[eo]) = make_uint2(q01, q23);
}

// ---------------------------------------------------------------------------
// Kernel 1: merged prep.
// job 0: zero border of g_xp (fp16 rows = 128B = 8 float4);
// job 1: fused weights bf16 hi/lo; job 2: offconv GEMM weights [10][32][64];
// job 3: padded depth plane.
// ---------------------------------------------------------------------------
#define NBORD_ (2*WP_ + 2*(HP_-2))   // 772
__global__ void prep_kernel(const float* __restrict__ w,
                            const float* __restrict__ w_off,
                            const float* __restrict__ depth) {
    int i = blockIdx.x * blockDim.x + threadIdx.x;
    int job = blockIdx.y;
    if (job == 0) {
        if (i >= B_ * NBORD_ * 8) return;
        int b   = i / (NBORD_ * 8);
        int r   = i % (NBORD_ * 8);
        int pix = r >> 3;
        int cq  = r & 7;
        int ph, pw;
        if (pix < WP_)            { ph = 0;        pw = pix; }
        else if (pix < 2*WP_)     { ph = HP_ - 1;  pw = pix - WP_; }
        else if (pix < 2*WP_ + (HP_-2)) { ph = pix - 2*WP_ + 1;  pw = 0; }
        else                      { ph = pix - (2*WP_ + (HP_-2)) + 1; pw = WP_ - 1; }
        reinterpret_cast<float4*>(g_xp + ((size_t)b * HPWP_ + ph * WP_ + pw) * C_)[cq] =
            make_float4(0.f, 0.f, 0.f, 0.f);
    } else if (job == 1) {
        if (i >= KK_*C_*C_) return;
        int kk = i / (C_*C_);
        int oc = (i >> 6) & 63;
        int c  = i & 63;
        float v = w[oc * 576 + c * KK_ + kk];
        uint16_t hb, lb; bf16_split(v, hb, lb);
        g_wtbh[(kk * C_ + oc) * C_ + c] = hb;
        g_wtbl[(kk * C_ + oc) * C_ + c] = lb;
    } else if (job == 2) {
        if (i >= 10*32*C_) return;
        int ch = i / (32*C_);
        int r  = i % (32*C_);
        int oc = r >> 6;
        int k  = r & 63;
        float v = 0.f;
        if (oc < OC_) {
            if (ch < 9)        v = w_off[(oc * CI_ + k) * KK_ + ch];   // x channel k, tap ch
            else if (k < KK_)  v = w_off[(oc * CI_ + 64) * KK_ + k];   // depth, tap k
        }
        uint16_t hb, lb; bf16_split(v, hb, lb);
        g_wobh[i] = hb;
        g_wobl[i] = lb;
    } else {
        if (i >= B_ * HPWP_) return;
        int b  = i / HPWP_;
        int pp = i % HPWP_;
        int ph = pp / WP_, pw = pp % WP_;
        float v = 0.f;
        if (ph >= 1 && ph <= H_ && pw >= 1 && pw <= W_)
            v = depth[(size_t)b * HW_ + (ph - 1) * W_ + (pw - 1)];
        g_dp[i] = v;
    }
}

// ---------------------------------------------------------------------------
// Kernel 2: NCHW fp32 -> padded NHWC fp16 transpose (interior)
// ---------------------------------------------------------------------------
__global__ __launch_bounds__(256) void nhwc_kernel(const float* __restrict__ x) {
    __shared__ float tile[C_][33];
    const int tid = threadIdx.x;
    const int b   = blockIdx.y;
    const int pix0 = blockIdx.x * 32;

    {
        int ty = tid >> 5, tx = tid & 31;
        #pragma unroll
        for (int c0 = 0; c0 < C_; c0 += 8)
            tile[c0 + ty][tx] = x[((size_t)b * C_ + c0 + ty) * HW_ + pix0 + tx];
    }
    __syncthreads();
    {
        int pi = tid >> 6, c = tid & 63;
        #pragma unroll
        for (int j = 0; j < 8; ++j) {
            int pix = pix0 + j * 4 + pi;
            int ph = pix / W_ + 1, pw = pix % W_ + 1;
            g_xp[((size_t)b * HPWP_ + ph * WP_ + pw) * C_ + c] =
                __float2half(tile[c][j * 4 + pi]);
        }
    }
}

// ---------------------------------------------------------------------------
// Kernel 3: offconv as mma.sync GEMM from padded NHWC fp16 x.
// Block: 128 px (M) x 24 oc (N, 18 used), 256 threads / 8 warps.
// K chunks 0..8 = x channels for tap ch (coalesced 128B fp16 rows);
// chunk 9 = depth taps (ki=0 only). Static smem 45 KB -> 4 blocks/SM.
// ---------------------------------------------------------------------------
#define APITCH_ 72

__global__ __launch_bounds__(256) void offmma_kernel(const float* __restrict__ bias)
{
    __shared__ __align__(16) uint16_t Ahi[128 * APITCH_];  // 18432 B
    __shared__ __align__(16) uint16_t Alo[128 * APITCH_];  // 18432 B
    __shared__ __align__(16) uint16_t Bhi[32 * APITCH_];   //  4608 B
    __shared__ __align__(16) uint16_t Blo[32 * APITCH_];   //  4608 B

    const int tid  = threadIdx.x;
    const int wid  = tid >> 5;
    const int lane = tid & 31;
    const int b    = blockIdx.y;
    const int pix0 = blockIdx.x * 128;

    const __half* xb = g_xp + (size_t)b * HPWP_ * C_;
    const float*  db = g_dp + (size_t)b * HPWP_;
    const int cg = tid & 15;    // channel group (4 ch)
    const int pb = tid >> 4;    // 0..15

    // fill A for chunk ch (x taps, or depth for ch==9)
    auto fillA = [&](int ch) {
        if (ch < 9) {
            const int dy = ch / 3, dx = ch % 3;   // padded-frame tap base
            #pragma unroll 2
            for (int i = 0; i < 8; ++i) {
                int p = pb + 16 * i;
                int pix = pix0 + p;
                int oh = pix / W_, ow = pix % W_;
                int idx = (oh + dy) * WP_ + (ow + dx);
                const uint2* q = reinterpret_cast<const uint2*>(xb + (size_t)idx * C_) + cg;
                split_store(Ahi, Alo, p * APITCH_ + cg * 4, h4_to_f4(q[0]));
            }
        } else {
            if (cg >= 4) return;                  // only cols 0..15 read (ki=0)
            #pragma unroll 2
            for (int i = 0; i < 8; ++i) {
                int p = pb + 16 * i;
                int pix = pix0 + p;
                int oh = pix / W_, ow = pix % W_;
                float4 v = make_float4(0.f, 0.f, 0.f, 0.f);
                float* ve = &v.x;
                #pragma unroll
                for (int e = 0; e < 4; ++e) {
                    int t = cg * 4 + e;
                    if (t < KK_)
                        ve[e] = db[(oh + t / 3) * WP_ + (ow + t % 3)];
                }
                split_store(Ahi, Alo, p * APITCH_ + cg * 4, v);
            }
        }
    };

    // stage B chunk into smem (coalesced uint2 copy, pitch 72)
    auto stageB = [&](int ch) {
        const uint2* sh = reinterpret_cast<const uint2*>(g_wobh + ch * (32*C_));
        const uint2* sl = reinterpret_cast<const uint2*>(g_wobl + ch * (32*C_));
        #pragma unroll
        for (int e = tid; e < 512; e += 256) {
            int oc = e >> 4, c4 = e & 15;
            int doff = oc * APITCH_ + c4 * 4;
            *reinterpret_cast<uint2*>(&Bhi[doff]) = sh[e];
            *reinterpret_cast<uint2*>(&Blo[doff]) = sl[e];
        }
    };

    float acc[3][4];
    #pragma unroll
    for (int ni = 0; ni < 3; ++ni)
        #pragma unroll
        for (int r = 0; r < 4; ++r) acc[ni][r] = 0.f;

    const int arow = wid * 16 + (lane >> 2);
    const int akol = (lane & 3) * 2;
    const int brow = lane >> 2;

    fillA(0);
    stageB(0);
    __syncthreads();

    for (int ch = 0; ch < 10; ++ch) {
        const int nki = (ch == 9) ? 1 : 4;
        for (int ki = 0; ki < nki; ++ki) {
            const int k0 = ki * 16 + akol;
            const int r0 = arow * APITCH_ + k0;
            const int r1 = r0 + 8 * APITCH_;
            uint32_t a0h = *reinterpret_cast<const uint32_t*>(&Ahi[r0]);
            uint32_t a1h = *reinterpret_cast<const uint32_t*>(&Ahi[r1]);
            uint32_t a2h = *reinterpret_cast<const uint32_t*>(&Ahi[r0 + 8]);
            uint32_t a3h = *reinterpret_cast<const uint32_t*>(&Ahi[r1 + 8]);
            uint32_t a0l = *reinterpret_cast<const uint32_t*>(&Alo[r0]);
            uint32_t a1l = *reinterpret_cast<const uint32_t*>(&Alo[r1]);
            uint32_t a2l = *reinterpret_cast<const uint32_t*>(&Alo[r0 + 8]);
            uint32_t a3l = *reinterpret_cast<const uint32_t*>(&Alo[r1 + 8]);
            #pragma unroll
            for (int ni = 0; ni < 3; ++ni) {      // 24 oc >= 18 used
                int boff = (brow + ni * 8) * APITCH_ + k0;
                uint32_t bh0 = *reinterpret_cast<const uint32_t*>(&Bhi[boff]);
                uint32_t bh1 = *reinterpret_cast<const uint32_t*>(&Bhi[boff + 8]);
                uint32_t bl0 = *reinterpret_cast<const uint32_t*>(&Blo[boff]);
                uint32_t bl1 = *reinterpret_cast<const uint32_t*>(&Blo[boff + 8]);
                float* d = acc[ni];
                mma16816(d[0], d[1], d[2], d[3], a0h, a1h, a2h, a3h, bh0, bh1);
                mma16816(d[0], d[1], d[2], d[3], a0l, a1l, a2l, a3l, bh0, bh1);
                mma16816(d[0], d[1], d[2], d[3], a0h, a1h, a2h, a3h, bl0, bl1);
            }
        }
        if (ch + 1 < 10) {
            __syncthreads();
            fillA(ch + 1);
            stageB(ch + 1);
            __syncthreads();
        }
    }

    // epilogue: [16px][24oc] per warp -> g_off[b][oc][px] (+bias), oc<18 only
    const int px = pix0 + wid * 16 + (lane >> 2);
    #pragma unroll
    for (int ni = 0; ni < 3; ++ni) {
        int oc = ni * 8 + (lane & 3) * 2;
        if (oc < OC_) {
            float b0 = bias[oc], b1 = bias[oc + 1];
            float* o0 = g_off + ((size_t)b * OC_ + oc) * HW_;
            float* o1 = g_off + ((size_t)b * OC_ + oc + 1) * HW_;
            o0[px]     = acc[ni][0] + b0;
            o1[px]     = acc[ni][1] + b1;
            o0[px + 8] = acc[ni][2] + b0;
            o1[px + 8] = acc[ni][3] + b1;
        }
    }
}

// ---------------------------------------------------------------------------
// Kernel 4: fused bilinear gather (fp16 source) + mma.sync bf16 GEMM.
// Block: 128 px x 64 oc, 256 threads / 8 warps. Single-buffered A + staged B.
// Taps computed for kk+1 during mma(kk). smem 55.5 KB -> 4 blocks/SM.
// ---------------------------------------------------------------------------
#define MPX_    128
#define ATILE_  (MPX_ * APITCH_)            // 9216 uint16
#define BTILE_  (C_ * APITCH_)              // 4608 uint16
#define SM_AHI  0
#define SM_ALO  (ATILE_ * 2)                // 18432
#define SM_BHI  (SM_ALO + ATILE_ * 2)       // 36864
#define SM_BLO  (SM_BHI + BTILE_ * 2)       // 46080
#define SM_TIDX (SM_BLO + BTILE_ * 2)       // 55296
#define SM_TA   (SM_TIDX + MPX_ * 4)        // 55808
#define SM_TOT  (SM_TA + MPX_ * 8)          // 56832

struct __align__(8) TapA { float ax, ay; };

__global__ __launch_bounds__(256, 4) void fused_mma_kernel(float* __restrict__ out)
{
    extern __shared__ char sm[];
    uint16_t* Ahi = reinterpret_cast<uint16_t*>(sm + SM_AHI);
    uint16_t* Alo = reinterpret_cast<uint16_t*>(sm + SM_ALO);
    uint16_t* Bhi = reinterpret_cast<uint16_t*>(sm + SM_BHI);
    uint16_t* Blo = reinterpret_cast<uint16_t*>(sm + SM_BLO);
    int*  tap_idx = reinterpret_cast<int*>(sm + SM_TIDX);
    TapA* tap_a   = reinterpret_cast<TapA*>(sm + SM_TA);

    const int tid  = threadIdx.x;
    const int wid  = tid >> 5;
    const int lane = tid & 31;
    const int b    = blockIdx.y;
    const int pix0 = blockIdx.x * MPX_;

    const int ocg = wid & 1;
    const int pxg = wid >> 1;

    float acc[2][4][4];
    #pragma unroll
    for (int mi = 0; mi < 2; ++mi)
        #pragma unroll
        for (int ni = 0; ni < 4; ++ni)
            #pragma unroll
            for (int r = 0; r < 4; ++r) acc[mi][ni][r] = 0.f;

    const __half* xb = g_xp + (size_t)b * HPWP_ * C_;
    const int cg = tid & 15;
    const int pb = tid >> 4;

    auto taps = [&](int kk) {
        if (tid < MPX_) {
            int pix = pix0 + tid;
            int oh = pix / W_, ow = pix % W_;
            float ox = g_off[((size_t)b * OC_ + kk) * HW_ + pix];
            float oy = g_off[((size_t)b * OC_ + KK_ + kk) * HW_ + pix];
            float cx = (float)(oh + kk / 3) + ox;
            float cy = (float)(ow + kk % 3) + oy;
            cx = fminf(fmaxf(cx, 0.f), (float)(HP_ - 1));
            cy = fminf(fmaxf(cy, 0.f), (float)(WP_ - 1));
            int tlx = (int)floorf(cx); tlx = min(max(tlx, 0), HP_ - 2);
            int tly = (int)floorf(cy); tly = min(max(tly, 0), WP_ - 2);
            tap_idx[tid] = tlx * WP_ + tly;
            tap_a[tid].ax = cx - (float)tlx;
            tap_a[tid].ay = cy - (float)tly;
        }
    };

    auto gather = [&]() {
        #pragma unroll 2
        for (int i = 0; i < 8; ++i) {
            int p = pb + 16 * i;
            int idx = tap_idx[p];
            TapA a = tap_a[p];
            const uint2* q = reinterpret_cast<const uint2*>(xb + (size_t)idx * C_) + cg;
            float4 x00 = h4_to_f4(q[0]);
            float4 x01 = h4_to_f4(q[16]);           // +1 col = +64 halfs
            float4 x10 = h4_to_f4(q[WP_ * 16]);     // +1 row
            float4 x11 = h4_to_f4(q[(WP_ + 1) * 16]);
            float4 v;
            {
                float r0, r1;
                r0 = fmaf(a.ay, x01.x - x00.x, x00.x);
                r1 = fmaf(a.ay, x11.x - x10.x, x10.x);
                v.x = fmaf(a.ax, r1 - r0, r0);
                r0 = fmaf(a.ay, x01.y - x00.y, x00.y);
                r1 = fmaf(a.ay, x11.y - x10.y, x10.y);
                v.y = fmaf(a.ax, r1 - r0, r0);
                r0 = fmaf(a.ay, x01.z - x00.z, x00.z);
                r1 = fmaf(a.ay, x11.z - x10.z, x10.z);
                v.z = fmaf(a.ax, r1 - r0, r0);
                r0 = fmaf(a.ay, x01.w - x00.w, x00.w);
                r1 = fmaf(a.ay, x11.w - x10.w, x10.w);
                v.w = fmaf(a.ax, r1 - r0, r0);
            }
            split_store(Ahi, Alo, p * APITCH_ + cg * 4, v);
        }
    };

    auto stageB = [&](int kk) {
        const uint2* sh = reinterpret_cast<const uint2*>(g_wtbh + kk * (C_*C_));
        const uint2* sl = reinterpret_cast<const uint2*>(g_wtbl + kk * (C_*C_));
        #pragma unroll
        for (int e = tid; e < 1024; e += 256) {
            int oc = e >> 4, c4 = e & 15;
            int doff = oc * APITCH_ + c4 * 4;
            *reinterpret_cast<uint2*>(&Bhi[doff]) = sh[e];
            *reinterpret_cast<uint2*>(&Blo[doff]) = sl[e];
        }
    };

    taps(0);
    __syncthreads();
    stageB(0);
    gather();
    __syncthreads();

    const int arow = pxg * 32 + (lane >> 2);
    const int akol = (lane & 3) * 2;
    const int brow = ocg * 32 + (lane >> 2);

    for (int kk = 0; kk < KK_; ++kk) {
        if (kk + 1 < KK_) taps(kk + 1);

        #pragma unroll
        for (int ki = 0; ki < 4; ++ki) {
            const int k0 = ki * 16 + akol;
            uint32_t ah[2][4], al[2][4];
            #pragma unroll
            for (int mi = 0; mi < 2; ++mi) {
                int r0 = (arow + mi * 16) * APITCH_ + k0;
                int r1 = r0 + 8 * APITCH_;
                ah[mi][0] = *reinterpret_cast<const uint32_t*>(&Ahi[r0]);
                ah[mi][1] = *reinterpret_cast<const uint32_t*>(&Ahi[r1]);
                ah[mi][2] = *reinterpret_cast<const uint32_t*>(&Ahi[r0 + 8]);
                ah[mi][3] = *reinterpret_cast<const uint32_t*>(&Ahi[r1 + 8]);
                al[mi][0] = *reinterpret_cast<const uint32_t*>(&Alo[r0]);
                al[mi][1] = *reinterpret_cast<const uint32_t*>(&Alo[r1]);
                al[mi][2] = *reinterpret_cast<const uint32_t*>(&Alo[r0 + 8]);
                al[mi][3] = *reinterpret_cast<const uint32_t*>(&Alo[r1 + 8]);
            }
            #pragma unroll
            for (int ni = 0; ni < 4; ++ni) {
                int boff = (brow + ni * 8) * APITCH_ + k0;
                uint32_t bh0 = *reinterpret_cast<const uint32_t*>(&Bhi[boff]);
                uint32_t bh1 = *reinterpret_cast<const uint32_t*>(&Bhi[boff + 8]);
                uint32_t bl0 = *reinterpret_cast<const uint32_t*>(&Blo[boff]);
                uint32_t bl1 = *reinterpret_cast<const uint32_t*>(&Blo[boff + 8]);
                #pragma unroll
                for (int mi = 0; mi < 2; ++mi) {
                    float* d = acc[mi][ni];
                    mma16816(d[0], d[1], d[2], d[3],
                             ah[mi][0], ah[mi][1], ah[mi][2], ah[mi][3], bh0, bh1);
                    mma16816(d[0], d[1], d[2], d[3],
                             al[mi][0], al[mi][1], al[mi][2], al[mi][3], bh0, bh1);
                    mma16816(d[0], d[1], d[2], d[3],
                             ah[mi][0], ah[mi][1], ah[mi][2], ah[mi][3], bl0, bl1);
                }
            }
        }
        if (kk + 1 < KK_) {
            __syncthreads();
            stageB(kk + 1);
            gather();
            __syncthreads();
        }
    }

    #pragma unroll
    for (int mi = 0; mi < 2; ++mi) {
        int px = pix0 + pxg * 32 + mi * 16 + (lane >> 2);
        #pragma unroll
        for (int ni = 0; ni < 4; ++ni) {
            int oc = ocg * 32 + ni * 8 + (lane & 3) * 2;
            float* o0 = out + ((size_t)b * C_ + oc) * HW_;
            float* o1 = out + ((size_t)b * C_ + oc + 1) * HW_;
            o0[px]     = acc[mi][ni][0];
            o1[px]     = acc[mi][ni][1];
            o0[px + 8] = acc[mi][ni][2];
            o1[px + 8] = acc[mi][ni][3];
        }
    }
}

// ---------------------------------------------------------------------------
// Launch
// ---------------------------------------------------------------------------
extern "C" void kernel_launch(void* const* d_in, const int* in_sizes, int n_in,
                              void* d_out, int out_size) {
    const float* x      = (const float*)d_in[0];
    const float* depth  = (const float*)d_in[1];
    const float* w_off  = (const float*)d_in[2];
    const float* bias   = (const float*)d_in[3];
    const float* weight = (const float*)d_in[4];
    float* out = (float*)d_out;

    {
        dim3 grid(295, 4);   // 295*256 = 75520 >= all job sizes
        prep_kernel<<<grid, 256>>>(weight, w_off, depth);
    }
    {
        dim3 grid(HW_ / 32, B_);
        nhwc_kernel<<<grid, 256>>>(x);
    }
    {
        dim3 grid(HW_ / 128, B_);
        offmma_kernel<<<grid, 256>>>(bias);
    }
    {
        static bool attr_set = false;
        if (!attr_set) {
            cudaFuncSetAttribute(fused_mma_kernel,
                                 cudaFuncAttributeMaxDynamicSharedMemorySize, SM_TOT);
            attr_set = true;
        }
        dim3 grid(HW_ / MPX_, B_);
        fused_mma_kernel<<<grid, 256, SM_TOT>>>(out);
    }
}

// round 15
// speedup vs baseline: 4.3253x; 1.2443x over previous
#include <cuda_runtime.h>
#include <cuda_bf16.h>
#include <cuda_fp16.h>
#include <cstdint>
#include <cstring>

// Problem constants
#define B_   2
#define C_   64
#define H_   192
#define W_   192
#define HW_  (H_*W_)          // 36864
#define KK_  9
#define HP_  194
#define WP_  194
#define HPWP_ (HP_*WP_)       // 37636
#define CI_  65               // C+1
#define OC_  18               // 2*KK

// Scratch (device globals)
__device__ __half   g_xp  [B_*HPWP_*C_];     // padded x, NHWC fp16 (~9.6 MB)
__device__ float    g_dp  [B_*HPWP_];        // padded depth (~0.3 MB)
__device__ float    g_off [B_*OC_*HW_];      // offsets (~5.3 MB)
__device__ uint16_t g_wtbh[KK_*C_*C_];       // fused weight hi fp16, [kk][oc][c]
__device__ uint16_t g_wtbl[KK_*C_*C_];       // fused weight lo fp16
__device__ uint16_t g_wobh[10*32*C_];        // offconv weight hi fp16
__device__ uint16_t g_wobl[10*32*C_];        // offconv weight lo fp16

// ---------------------------------------------------------------------------
// helpers
// ---------------------------------------------------------------------------
__device__ __forceinline__ float4 h4_to_f4(uint2 u) {
    __half2 h0 = *reinterpret_cast<__half2*>(&u.x);
    __half2 h1 = *reinterpret_cast<__half2*>(&u.y);
    float2 f0 = __half22float2(h0);
    float2 f1 = __half22float2(h1);
    return make_float4(f0.x, f0.y, f1.x, f1.y);
}

__device__ __forceinline__ uint2 f4_to_h4(float4 v) {
    __half2 h0 = __floats2half2_rn(v.x, v.y);
    __half2 h1 = __floats2half2_rn(v.z, v.w);
    uint2 r;
    memcpy(&r.x, &h0, 4);
    memcpy(&r.y, &h1, 4);
    return r;
}

// f16 mma: D(f32) += A(f16) * B(f16)
__device__ __forceinline__ void mma16816(float& d0, float& d1, float& d2, float& d3,
                                         uint32_t a0, uint32_t a1, uint32_t a2, uint32_t a3,
                                         uint32_t b0, uint32_t b1) {
    asm volatile("mma.sync.aligned.m16n8k16.row.col.f32.f16.f16.f32 "
                 "{%0,%1,%2,%3},{%4,%5,%6,%7},{%8,%9},{%0,%1,%2,%3};"
                 : "+f"(d0), "+f"(d1), "+f"(d2), "+f"(d3)
                 : "r"(a0), "r"(a1), "r"(a2), "r"(a3), "r"(b0), "r"(b1));
}

__device__ __forceinline__ void fp16_split(float v, uint16_t& h, uint16_t& l) {
    __half hb = __float2half_rn(v);
    float hf = __half2float(hb);
    __half lb = __float2half_rn(v - hf);
    memcpy(&h, &hb, 2); memcpy(&l, &lb, 2);
}

// ---------------------------------------------------------------------------
// Kernel 1: merged prep.
// job 0: zero border of g_xp; job 1: fused weights fp16 hi/lo;
// job 2: offconv GEMM weights [10][32][64]; job 3: padded depth plane.
// ---------------------------------------------------------------------------
#define NBORD_ (2*WP_ + 2*(HP_-2))   // 772
__global__ void prep_kernel(const float* __restrict__ w,
                            const float* __restrict__ w_off,
                            const float* __restrict__ depth) {
    int i = blockIdx.x * blockDim.x + threadIdx.x;
    int job = blockIdx.y;
    if (job == 0) {
        if (i >= B_ * NBORD_ * 8) return;
        int b   = i / (NBORD_ * 8);
        int r   = i % (NBORD_ * 8);
        int pix = r >> 3;
        int cq  = r & 7;
        int ph, pw;
        if (pix < WP_)            { ph = 0;        pw = pix; }
        else if (pix < 2*WP_)     { ph = HP_ - 1;  pw = pix - WP_; }
        else if (pix < 2*WP_ + (HP_-2)) { ph = pix - 2*WP_ + 1;  pw = 0; }
        else                      { ph = pix - (2*WP_ + (HP_-2)) + 1; pw = WP_ - 1; }
        reinterpret_cast<float4*>(g_xp + ((size_t)b * HPWP_ + ph * WP_ + pw) * C_)[cq] =
            make_float4(0.f, 0.f, 0.f, 0.f);
    } else if (job == 1) {
        if (i >= KK_*C_*C_) return;
        int kk = i / (C_*C_);
        int oc = (i >> 6) & 63;
        int c  = i & 63;
        float v = w[oc * 576 + c * KK_ + kk];
        uint16_t hb, lb; fp16_split(v, hb, lb);
        g_wtbh[(kk * C_ + oc) * C_ + c] = hb;
        g_wtbl[(kk * C_ + oc) * C_ + c] = lb;
    } else if (job == 2) {
        if (i >= 10*32*C_) return;
        int ch = i / (32*C_);
        int r  = i % (32*C_);
        int oc = r >> 6;
        int k  = r & 63;
        float v = 0.f;
        if (oc < OC_) {
            if (ch < 9)        v = w_off[(oc * CI_ + k) * KK_ + ch];   // x channel k, tap ch
            else if (k < KK_)  v = w_off[(oc * CI_ + 64) * KK_ + k];   // depth, tap k
        }
        uint16_t hb, lb; fp16_split(v, hb, lb);
        g_wobh[i] = hb;
        g_wobl[i] = lb;
    } else {
        if (i >= B_ * HPWP_) return;
        int b  = i / HPWP_;
        int pp = i % HPWP_;
        int ph = pp / WP_, pw = pp % WP_;
        float v = 0.f;
        if (ph >= 1 && ph <= H_ && pw >= 1 && pw <= W_)
            v = depth[(size_t)b * HW_ + (ph - 1) * W_ + (pw - 1)];
        g_dp[i] = v;
    }
}

// ---------------------------------------------------------------------------
// Kernel 2: NCHW fp32 -> padded NHWC fp16 transpose (interior)
// ---------------------------------------------------------------------------
__global__ __launch_bounds__(256) void nhwc_kernel(const float* __restrict__ x) {
    __shared__ float tile[C_][33];
    const int tid = threadIdx.x;
    const int b   = blockIdx.y;
    const int pix0 = blockIdx.x * 32;

    {
        int ty = tid >> 5, tx = tid & 31;
        #pragma unroll
        for (int c0 = 0; c0 < C_; c0 += 8)
            tile[c0 + ty][tx] = x[((size_t)b * C_ + c0 + ty) * HW_ + pix0 + tx];
    }
    __syncthreads();
    {
        int pi = tid >> 6, c = tid & 63;
        #pragma unroll
        for (int j = 0; j < 8; ++j) {
            int pix = pix0 + j * 4 + pi;
            int ph = pix / W_ + 1, pw = pix % W_ + 1;
            g_xp[((size_t)b * HPWP_ + ph * WP_ + pw) * C_ + c] =
                __float2half(tile[c][j * 4 + pi]);
        }
    }
}

// ---------------------------------------------------------------------------
// Kernel 3: offconv as mma.sync f16 GEMM (A single-term, B hi/lo 2-term).
// Block: 128 px (M) x 24 oc (N, 18 used), 256 threads / 8 warps.
// ---------------------------------------------------------------------------
#define APITCH_ 72

__global__ __launch_bounds__(256) void offmma_kernel(const float* __restrict__ bias)
{
    __shared__ __align__(16) uint16_t Aa [128 * APITCH_];  // 18432 B
    __shared__ __align__(16) uint16_t Bhi[32 * APITCH_];   //  4608 B
    __shared__ __align__(16) uint16_t Blo[32 * APITCH_];   //  4608 B

    const int tid  = threadIdx.x;
    const int wid  = tid >> 5;
    const int lane = tid & 31;
    const int b    = blockIdx.y;
    const int pix0 = blockIdx.x * 128;

    const __half* xb = g_xp + (size_t)b * HPWP_ * C_;
    const float*  db = g_dp + (size_t)b * HPWP_;
    const int cg = tid & 15;    // channel group (4 ch)
    const int pb = tid >> 4;    // 0..15

    // fill A for chunk ch (x taps, or depth for ch==9)
    auto fillA = [&](int ch) {
        if (ch < 9) {
            const int dy = ch / 3, dx = ch % 3;
            #pragma unroll 2
            for (int i = 0; i < 8; ++i) {
                int p = pb + 16 * i;
                int pix = pix0 + p;
                int oh = pix / W_, ow = pix % W_;
                int idx = (oh + dy) * WP_ + (ow + dx);
                const uint2* q = reinterpret_cast<const uint2*>(xb + (size_t)idx * C_) + cg;
                *reinterpret_cast<uint2*>(&Aa[p * APITCH_ + cg * 4]) = q[0];
            }
        } else {
            if (cg >= 4) return;                  // only cols 0..15 read (ki=0)
            #pragma unroll 2
            for (int i = 0; i < 8; ++i) {
                int p = pb + 16 * i;
                int pix = pix0 + p;
                int oh = pix / W_, ow = pix % W_;
                float4 v = make_float4(0.f, 0.f, 0.f, 0.f);
                float* ve = &v.x;
                #pragma unroll
                for (int e = 0; e < 4; ++e) {
                    int t = cg * 4 + e;
                    if (t < KK_)
                        ve[e] = db[(oh + t / 3) * WP_ + (ow + t % 3)];
                }
                *reinterpret_cast<uint2*>(&Aa[p * APITCH_ + cg * 4]) = f4_to_h4(v);
            }
        }
    };

    auto stageB = [&](int ch) {
        const uint2* sh = reinterpret_cast<const uint2*>(g_wobh + ch * (32*C_));
        const uint2* sl = reinterpret_cast<const uint2*>(g_wobl + ch * (32*C_));
        #pragma unroll
        for (int e = tid; e < 512; e += 256) {
            int oc = e >> 4, c4 = e & 15;
            int doff = oc * APITCH_ + c4 * 4;
            *reinterpret_cast<uint2*>(&Bhi[doff]) = sh[e];
            *reinterpret_cast<uint2*>(&Blo[doff]) = sl[e];
        }
    };

    float acc[3][4];
    #pragma unroll
    for (int ni = 0; ni < 3; ++ni)
        #pragma unroll
        for (int r = 0; r < 4; ++r) acc[ni][r] = 0.f;

    const int arow = wid * 16 + (lane >> 2);
    const int akol = (lane & 3) * 2;
    const int brow = lane >> 2;

    fillA(0);
    stageB(0);
    __syncthreads();

    for (int ch = 0; ch < 10; ++ch) {
        const int nki = (ch == 9) ? 1 : 4;
        for (int ki = 0; ki < nki; ++ki) {
            const int k0 = ki * 16 + akol;
            const int r0 = arow * APITCH_ + k0;
            const int r1 = r0 + 8 * APITCH_;
            uint32_t a0 = *reinterpret_cast<const uint32_t*>(&Aa[r0]);
            uint32_t a1 = *reinterpret_cast<const uint32_t*>(&Aa[r1]);
            uint32_t a2 = *reinterpret_cast<const uint32_t*>(&Aa[r0 + 8]);
            uint32_t a3 = *reinterpret_cast<const uint32_t*>(&Aa[r1 + 8]);
            #pragma unroll
            for (int ni = 0; ni < 3; ++ni) {
                int boff = (brow + ni * 8) * APITCH_ + k0;
                uint32_t bh0 = *reinterpret_cast<const uint32_t*>(&Bhi[boff]);
                uint32_t bh1 = *reinterpret_cast<const uint32_t*>(&Bhi[boff + 8]);
                uint32_t bl0 = *reinterpret_cast<const uint32_t*>(&Blo[boff]);
                uint32_t bl1 = *reinterpret_cast<const uint32_t*>(&Blo[boff + 8]);
                float* d = acc[ni];
                mma16816(d[0], d[1], d[2], d[3], a0, a1, a2, a3, bh0, bh1);
                mma16816(d[0], d[1], d[2], d[3], a0, a1, a2, a3, bl0, bl1);
            }
        }
        if (ch + 1 < 10) {
            __syncthreads();
            fillA(ch + 1);
            stageB(ch + 1);
            __syncthreads();
        }
    }

    // epilogue: [16px][24oc] per warp -> g_off[b][oc][px] (+bias), oc<18 only
    const int px = pix0 + wid * 16 + (lane >> 2);
    #pragma unroll
    for (int ni = 0; ni < 3; ++ni) {
        int oc = ni * 8 + (lane & 3) * 2;
        if (oc < OC_) {
            float b0 = bias[oc], b1 = bias[oc + 1];
            float* o0 = g_off + ((size_t)b * OC_ + oc) * HW_;
            float* o1 = g_off + ((size_t)b * OC_ + oc + 1) * HW_;
            o0[px]     = acc[ni][0] + b0;
            o1[px]     = acc[ni][1] + b1;
            o0[px + 8] = acc[ni][2] + b0;
            o1[px + 8] = acc[ni][3] + b1;
        }
    }
}

// ---------------------------------------------------------------------------
// Kernel 4: fused bilinear gather (fp16) + f16 mma (A single, B hi/lo).
// Block: 128 px x 64 oc, 256 threads / 8 warps. smem ~38.5 KB.
// ---------------------------------------------------------------------------
#define MPX_    128
#define ATILE_  (MPX_ * APITCH_)            // 9216 uint16
#define BTILE_  (C_ * APITCH_)              // 4608 uint16
#define SM_A    0
#define SM_BHI  (ATILE_ * 2)                // 18432
#define SM_BLO  (SM_BHI + BTILE_ * 2)       // 27648
#define SM_TIDX (SM_BLO + BTILE_ * 2)       // 36864
#define SM_TA   (SM_TIDX + MPX_ * 4)        // 37376
#define SM_TOT  (SM_TA + MPX_ * 8)          // 38400

struct __align__(8) TapA { float ax, ay; };

__global__ __launch_bounds__(256, 4) void fused_mma_kernel(float* __restrict__ out)
{
    extern __shared__ char sm[];
    uint16_t* Aa  = reinterpret_cast<uint16_t*>(sm + SM_A);
    uint16_t* Bhi = reinterpret_cast<uint16_t*>(sm + SM_BHI);
    uint16_t* Blo = reinterpret_cast<uint16_t*>(sm + SM_BLO);
    int*  tap_idx = reinterpret_cast<int*>(sm + SM_TIDX);
    TapA* tap_a   = reinterpret_cast<TapA*>(sm + SM_TA);

    const int tid  = threadIdx.x;
    const int wid  = tid >> 5;
    const int lane = tid & 31;
    const int b    = blockIdx.y;
    const int pix0 = blockIdx.x * MPX_;

    const int ocg = wid & 1;
    const int pxg = wid >> 1;

    float acc[2][4][4];
    #pragma unroll
    for (int mi = 0; mi < 2; ++mi)
        #pragma unroll
        for (int ni = 0; ni < 4; ++ni)
            #pragma unroll
            for (int r = 0; r < 4; ++r) acc[mi][ni][r] = 0.f;

    const __half* xb = g_xp + (size_t)b * HPWP_ * C_;
    const int cg = tid & 15;
    const int pb = tid >> 4;

    auto taps = [&](int kk) {
        if (tid < MPX_) {
            int pix = pix0 + tid;
            int oh = pix / W_, ow = pix % W_;
            float ox = g_off[((size_t)b * OC_ + kk) * HW_ + pix];
            float oy = g_off[((size_t)b * OC_ + KK_ + kk) * HW_ + pix];
            float cx = (float)(oh + kk / 3) + ox;
            float cy = (float)(ow + kk % 3) + oy;
            cx = fminf(fmaxf(cx, 0.f), (float)(HP_ - 1));
            cy = fminf(fmaxf(cy, 0.f), (float)(WP_ - 1));
            int tlx = (int)floorf(cx); tlx = min(max(tlx, 0), HP_ - 2);
            int tly = (int)floorf(cy); tly = min(max(tly, 0), WP_ - 2);
            tap_idx[tid] = tlx * WP_ + tly;
            tap_a[tid].ax = cx - (float)tlx;
            tap_a[tid].ay = cy - (float)tly;
        }
    };

    auto gather = [&]() {
        #pragma unroll 2
        for (int i = 0; i < 8; ++i) {
            int p = pb + 16 * i;
            int idx = tap_idx[p];
            TapA a = tap_a[p];
            const uint2* q = reinterpret_cast<const uint2*>(xb + (size_t)idx * C_) + cg;
            float4 x00 = h4_to_f4(q[0]);
            float4 x01 = h4_to_f4(q[16]);           // +1 col = +64 halfs
            float4 x10 = h4_to_f4(q[WP_ * 16]);     // +1 row
            float4 x11 = h4_to_f4(q[(WP_ + 1) * 16]);
            float4 v;
            {
                float r0, r1;
                r0 = fmaf(a.ay, x01.x - x00.x, x00.x);
                r1 = fmaf(a.ay, x11.x - x10.x, x10.x);
                v.x = fmaf(a.ax, r1 - r0, r0);
                r0 = fmaf(a.ay, x01.y - x00.y, x00.y);
                r1 = fmaf(a.ay, x11.y - x10.y, x10.y);
                v.y = fmaf(a.ax, r1 - r0, r0);
                r0 = fmaf(a.ay, x01.z - x00.z, x00.z);
                r1 = fmaf(a.ay, x11.z - x10.z, x10.z);
                v.z = fmaf(a.ax, r1 - r0, r0);
                r0 = fmaf(a.ay, x01.w - x00.w, x00.w);
                r1 = fmaf(a.ay, x11.w - x10.w, x10.w);
                v.w = fmaf(a.ax, r1 - r0, r0);
            }
            *reinterpret_cast<uint2*>(&Aa[p * APITCH_ + cg * 4]) = f4_to_h4(v);
        }
    };

    auto stageB = [&](int kk) {
        const uint2* sh = reinterpret_cast<const uint2*>(g_wtbh + kk * (C_*C_));
        const uint2* sl = reinterpret_cast<const uint2*>(g_wtbl + kk * (C_*C_));
        #pragma unroll
        for (int e = tid; e < 1024; e += 256) {
            int oc = e >> 4, c4 = e & 15;
            int doff = oc * APITCH_ + c4 * 4;
            *reinterpret_cast<uint2*>(&Bhi[doff]) = sh[e];
            *reinterpret_cast<uint2*>(&Blo[doff]) = sl[e];
        }
    };

    taps(0);
    __syncthreads();
    stageB(0);
    gather();
    __syncthreads();

    const int arow = pxg * 32 + (lane >> 2);
    const int akol = (lane & 3) * 2;
    const int brow = ocg * 32 + (lane >> 2);

    for (int kk = 0; kk < KK_; ++kk) {
        if (kk + 1 < KK_) taps(kk + 1);

        #pragma unroll
        for (int ki = 0; ki < 4; ++ki) {
            const int k0 = ki * 16 + akol;
            uint32_t a[2][4];
            #pragma unroll
            for (int mi = 0; mi < 2; ++mi) {
                int r0 = (arow + mi * 16) * APITCH_ + k0;
                int r1 = r0 + 8 * APITCH_;
                a[mi][0] = *reinterpret_cast<const uint32_t*>(&Aa[r0]);
                a[mi][1] = *reinterpret_cast<const uint32_t*>(&Aa[r1]);
                a[mi][2] = *reinterpret_cast<const uint32_t*>(&Aa[r0 + 8]);
                a[mi][3] = *reinterpret_cast<const uint32_t*>(&Aa[r1 + 8]);
            }
            #pragma unroll
            for (int ni = 0; ni < 4; ++ni) {
                int boff = (brow + ni * 8) * APITCH_ + k0;
                uint32_t bh0 = *reinterpret_cast<const uint32_t*>(&Bhi[boff]);
                uint32_t bh1 = *reinterpret_cast<const uint32_t*>(&Bhi[boff + 8]);
                uint32_t bl0 = *reinterpret_cast<const uint32_t*>(&Blo[boff]);
                uint32_t bl1 = *reinterpret_cast<const uint32_t*>(&Blo[boff + 8]);
                #pragma unroll
                for (int mi = 0; mi < 2; ++mi) {
                    float* d = acc[mi][ni];
                    mma16816(d[0], d[1], d[2], d[3],
                             a[mi][0], a[mi][1], a[mi][2], a[mi][3], bh0, bh1);
                    mma16816(d[0], d[1], d[2], d[3],
                             a[mi][0], a[mi][1], a[mi][2], a[mi][3], bl0, bl1);
                }
            }
        }
        if (kk + 1 < KK_) {
            __syncthreads();
            stageB(kk + 1);
            gather();
            __syncthreads();
        }
    }

    #pragma unroll
    for (int mi = 0; mi < 2; ++mi) {
        int px = pix0 + pxg * 32 + mi * 16 + (lane >> 2);
        #pragma unroll
        for (int ni = 0; ni < 4; ++ni) {
            int oc = ocg * 32 + ni * 8 + (lane & 3) * 2;
            float* o0 = out + ((size_t)b * C_ + oc) * HW_;
            float* o1 = out + ((size_t)b * C_ + oc + 1) * HW_;
            o0[px]     = acc[mi][ni][0];
            o1[px]     = acc[mi][ni][1];
            o0[px + 8] = acc[mi][ni][2];
            o1[px + 8] = acc[mi][ni][3];
        }
    }
}

// ---------------------------------------------------------------------------
// Launch
// ---------------------------------------------------------------------------
extern "C" void kernel_launch(void* const* d_in, const int* in_sizes, int n_in,
                              void* d_out, int out_size) {
    const float* x      = (const float*)d_in[0];
    const float* depth  = (const float*)d_in[1];
    const float* w_off  = (const float*)d_in[2];
    const float* bias   = (const float*)d_in[3];
    const float* weight = (const float*)d_in[4];
    float* out = (float*)d_out;

    {
        dim3 grid(295, 4);   // 295*256 = 75520 >= all job sizes
        prep_kernel<<<grid, 256>>>(weight, w_off, depth);
    }
    {
        dim3 grid(HW_ / 32, B_);
        nhwc_kernel<<<grid, 256>>>(x);
    }
    {
        dim3 grid(HW_ / 128, B_);
        offmma_kernel<<<grid, 256>>>(bias);
    }
    {
        static bool attr_set = false;
        if (!attr_set) {
            cudaFuncSetAttribute(fused_mma_kernel,
                                 cudaFuncAttributeMaxDynamicSharedMemorySize, SM_TOT);
            attr_set = true;
        }
        dim3 grid(HW_ / MPX_, B_);
        fused_mma_kernel<<<grid, 256, SM_TOT>>>(out);
    }
}

// round 16
// speedup vs baseline: 4.6611x; 1.0777x over previous
#include <cuda_runtime.h>
#include <cuda_bf16.h>
#include <cuda_fp16.h>
#include <cstdint>
#include <cstring>

// Problem constants
#define B_   2
#define C_   64
#define H_   192
#define W_   192
#define HW_  (H_*W_)          // 36864
#define KK_  9
#define HP_  194
#define WP_  194
#define HPWP_ (HP_*WP_)       // 37636
#define CI_  65               // C+1
#define OC_  18               // 2*KK

// Scratch (device globals)
__device__ __half   g_xp  [B_*HPWP_*C_];     // padded x, NHWC fp16 (~9.6 MB)
__device__ float    g_dp  [B_*HPWP_];        // padded depth (~0.3 MB)
__device__ float    g_off [B_*OC_*HW_];      // offsets (~5.3 MB)
__device__ uint16_t g_wtbh[KK_*C_*C_];       // fused weight hi fp16, [kk][oc][c]
__device__ uint16_t g_wtbl[KK_*C_*C_];       // fused weight lo fp16
__device__ uint16_t g_wobh[10*32*C_];        // offconv weight hi fp16
__device__ uint16_t g_wobl[10*32*C_];        // offconv weight lo fp16

// ---------------------------------------------------------------------------
// helpers
// ---------------------------------------------------------------------------
__device__ __forceinline__ uint2 f4_to_h4(float4 v) {
    __half2 h0 = __floats2half2_rn(v.x, v.y);
    __half2 h1 = __floats2half2_rn(v.z, v.w);
    uint2 r;
    memcpy(&r.x, &h0, 4);
    memcpy(&r.y, &h1, 4);
    return r;
}

// f16 mma: D(f32) += A(f16) * B(f16)
__device__ __forceinline__ void mma16816(float& d0, float& d1, float& d2, float& d3,
                                         uint32_t a0, uint32_t a1, uint32_t a2, uint32_t a3,
                                         uint32_t b0, uint32_t b1) {
    asm volatile("mma.sync.aligned.m16n8k16.row.col.f32.f16.f16.f32 "
                 "{%0,%1,%2,%3},{%4,%5,%6,%7},{%8,%9},{%0,%1,%2,%3};"
                 : "+f"(d0), "+f"(d1), "+f"(d2), "+f"(d3)
                 : "r"(a0), "r"(a1), "r"(a2), "r"(a3), "r"(b0), "r"(b1));
}

__device__ __forceinline__ void fp16_split(float v, uint16_t& h, uint16_t& l) {
    __half hb = __float2half_rn(v);
    float hf = __half2float(hb);
    __half lb = __float2half_rn(v - hf);
    memcpy(&h, &hb, 2); memcpy(&l, &lb, 2);
}

// half2 lerp: r = a*(y-x) + x
__device__ __forceinline__ __half2 h2lerp(__half2 a, __half2 x, __half2 y) {
    return __hfma2(a, __hsub2(y, x), x);
}

// ---------------------------------------------------------------------------
// Kernel 1: merged prep.
// job 0: zero border of g_xp; job 1: fused weights fp16 hi/lo;
// job 2: offconv GEMM weights [10][32][64]; job 3: padded depth plane.
// ---------------------------------------------------------------------------
#define NBORD_ (2*WP_ + 2*(HP_-2))   // 772
__global__ void prep_kernel(const float* __restrict__ w,
                            const float* __restrict__ w_off,
                            const float* __restrict__ depth) {
    int i = blockIdx.x * blockDim.x + threadIdx.x;
    int job = blockIdx.y;
    if (job == 0) {
        if (i >= B_ * NBORD_ * 8) return;
        int b   = i / (NBORD_ * 8);
        int r   = i % (NBORD_ * 8);
        int pix = r >> 3;
        int cq  = r & 7;
        int ph, pw;
        if (pix < WP_)            { ph = 0;        pw = pix; }
        else if (pix < 2*WP_)     { ph = HP_ - 1;  pw = pix - WP_; }
        else if (pix < 2*WP_ + (HP_-2)) { ph = pix - 2*WP_ + 1;  pw = 0; }
        else                      { ph = pix - (2*WP_ + (HP_-2)) + 1; pw = WP_ - 1; }
        reinterpret_cast<float4*>(g_xp + ((size_t)b * HPWP_ + ph * WP_ + pw) * C_)[cq] =
            make_float4(0.f, 0.f, 0.f, 0.f);
    } else if (job == 1) {
        if (i >= KK_*C_*C_) return;
        int kk = i / (C_*C_);
        int oc = (i >> 6) & 63;
        int c  = i & 63;
        float v = w[oc * 576 + c * KK_ + kk];
        uint16_t hb, lb; fp16_split(v, hb, lb);
        g_wtbh[(kk * C_ + oc) * C_ + c] = hb;
        g_wtbl[(kk * C_ + oc) * C_ + c] = lb;
    } else if (job == 2) {
        if (i >= 10*32*C_) return;
        int ch = i / (32*C_);
        int r  = i % (32*C_);
        int oc = r >> 6;
        int k  = r & 63;
        float v = 0.f;
        if (oc < OC_) {
            if (ch < 9)        v = w_off[(oc * CI_ + k) * KK_ + ch];   // x channel k, tap ch
            else if (k < KK_)  v = w_off[(oc * CI_ + 64) * KK_ + k];   // depth, tap k
        }
        uint16_t hb, lb; fp16_split(v, hb, lb);
        g_wobh[i] = hb;
        g_wobl[i] = lb;
    } else {
        if (i >= B_ * HPWP_) return;
        int b  = i / HPWP_;
        int pp = i % HPWP_;
        int ph = pp / WP_, pw = pp % WP_;
        float v = 0.f;
        if (ph >= 1 && ph <= H_ && pw >= 1 && pw <= W_)
            v = depth[(size_t)b * HW_ + (ph - 1) * W_ + (pw - 1)];
        g_dp[i] = v;
    }
}

// ---------------------------------------------------------------------------
// Kernel 2: NCHW fp32 -> padded NHWC fp16 transpose (interior)
// ---------------------------------------------------------------------------
__global__ __launch_bounds__(256) void nhwc_kernel(const float* __restrict__ x) {
    __shared__ float tile[C_][33];
    const int tid = threadIdx.x;
    const int b   = blockIdx.y;
    const int pix0 = blockIdx.x * 32;

    {
        int ty = tid >> 5, tx = tid & 31;
        #pragma unroll
        for (int c0 = 0; c0 < C_; c0 += 8)
            tile[c0 + ty][tx] = x[((size_t)b * C_ + c0 + ty) * HW_ + pix0 + tx];
    }
    __syncthreads();
    {
        int pi = tid >> 6, c = tid & 63;
        #pragma unroll
        for (int j = 0; j < 8; ++j) {
            int pix = pix0 + j * 4 + pi;
            int ph = pix / W_ + 1, pw = pix % W_ + 1;
            g_xp[((size_t)b * HPWP_ + ph * WP_ + pw) * C_ + c] =
                __float2half(tile[c][j * 4 + pi]);
        }
    }
}

// ---------------------------------------------------------------------------
// Kernel 3: offconv as mma.sync f16 GEMM (A single-term, B hi/lo 2-term).
// Block: 128 px (M) x 24 oc (N, 18 used), 256 threads / 8 warps.
// ---------------------------------------------------------------------------
#define APITCH_ 72

__global__ __launch_bounds__(256) void offmma_kernel(const float* __restrict__ bias)
{
    __shared__ __align__(16) uint16_t Aa [128 * APITCH_];  // 18432 B
    __shared__ __align__(16) uint16_t Bhi[32 * APITCH_];   //  4608 B
    __shared__ __align__(16) uint16_t Blo[32 * APITCH_];   //  4608 B

    const int tid  = threadIdx.x;
    const int wid  = tid >> 5;
    const int lane = tid & 31;
    const int b    = blockIdx.y;
    const int pix0 = blockIdx.x * 128;

    const __half* xb = g_xp + (size_t)b * HPWP_ * C_;
    const float*  db = g_dp + (size_t)b * HPWP_;
    const int cg = tid & 15;    // channel group (4 ch)
    const int pb = tid >> 4;    // 0..15

    auto fillA = [&](int ch) {
        if (ch < 9) {
            const int dy = ch / 3, dx = ch % 3;
            #pragma unroll 2
            for (int i = 0; i < 8; ++i) {
                int p = pb + 16 * i;
                int pix = pix0 + p;
                int oh = pix / W_, ow = pix % W_;
                int idx = (oh + dy) * WP_ + (ow + dx);
                const uint2* q = reinterpret_cast<const uint2*>(xb + (size_t)idx * C_) + cg;
                *reinterpret_cast<uint2*>(&Aa[p * APITCH_ + cg * 4]) = q[0];
            }
        } else {
            if (cg >= 4) return;                  // only cols 0..15 read (ki=0)
            #pragma unroll 2
            for (int i = 0; i < 8; ++i) {
                int p = pb + 16 * i;
                int pix = pix0 + p;
                int oh = pix / W_, ow = pix % W_;
                float4 v = make_float4(0.f, 0.f, 0.f, 0.f);
                float* ve = &v.x;
                #pragma unroll
                for (int e = 0; e < 4; ++e) {
                    int t = cg * 4 + e;
                    if (t < KK_)
                        ve[e] = db[(oh + t / 3) * WP_ + (ow + t % 3)];
                }
                *reinterpret_cast<uint2*>(&Aa[p * APITCH_ + cg * 4]) = f4_to_h4(v);
            }
        }
    };

    auto stageB = [&](int ch) {
        const uint2* sh = reinterpret_cast<const uint2*>(g_wobh + ch * (32*C_));
        const uint2* sl = reinterpret_cast<const uint2*>(g_wobl + ch * (32*C_));
        #pragma unroll
        for (int e = tid; e < 512; e += 256) {
            int oc = e >> 4, c4 = e & 15;
            int doff = oc * APITCH_ + c4 * 4;
            *reinterpret_cast<uint2*>(&Bhi[doff]) = sh[e];
            *reinterpret_cast<uint2*>(&Blo[doff]) = sl[e];
        }
    };

    float acc[3][4];
    #pragma unroll
    for (int ni = 0; ni < 3; ++ni)
        #pragma unroll
        for (int r = 0; r < 4; ++r) acc[ni][r] = 0.f;

    const int arow = wid * 16 + (lane >> 2);
    const int akol = (lane & 3) * 2;
    const int brow = lane >> 2;

    fillA(0);
    stageB(0);
    __syncthreads();

    for (int ch = 0; ch < 10; ++ch) {
        const int nki = (ch == 9) ? 1 : 4;
        for (int ki = 0; ki < nki; ++ki) {
            const int k0 = ki * 16 + akol;
            const int r0 = arow * APITCH_ + k0;
            const int r1 = r0 + 8 * APITCH_;
            uint32_t a0 = *reinterpret_cast<const uint32_t*>(&Aa[r0]);
            uint32_t a1 = *reinterpret_cast<const uint32_t*>(&Aa[r1]);
            uint32_t a2 = *reinterpret_cast<const uint32_t*>(&Aa[r0 + 8]);
            uint32_t a3 = *reinterpret_cast<const uint32_t*>(&Aa[r1 + 8]);
            #pragma unroll
            for (int ni = 0; ni < 3; ++ni) {
                int boff = (brow + ni * 8) * APITCH_ + k0;
                uint32_t bh0 = *reinterpret_cast<const uint32_t*>(&Bhi[boff]);
                uint32_t bh1 = *reinterpret_cast<const uint32_t*>(&Bhi[boff + 8]);
                uint32_t bl0 = *reinterpret_cast<const uint32_t*>(&Blo[boff]);
                uint32_t bl1 = *reinterpret_cast<const uint32_t*>(&Blo[boff + 8]);
                float* d = acc[ni];
                mma16816(d[0], d[1], d[2], d[3], a0, a1, a2, a3, bh0, bh1);
                mma16816(d[0], d[1], d[2], d[3], a0, a1, a2, a3, bl0, bl1);
            }
        }
        if (ch + 1 < 10) {
            __syncthreads();
            fillA(ch + 1);
            stageB(ch + 1);
            __syncthreads();
        }
    }

    const int px = pix0 + wid * 16 + (lane >> 2);
    #pragma unroll
    for (int ni = 0; ni < 3; ++ni) {
        int oc = ni * 8 + (lane & 3) * 2;
        if (oc < OC_) {
            float b0 = bias[oc], b1 = bias[oc + 1];
            float* o0 = g_off + ((size_t)b * OC_ + oc) * HW_;
            float* o1 = g_off + ((size_t)b * OC_ + oc + 1) * HW_;
            o0[px]     = acc[ni][0] + b0;
            o1[px]     = acc[ni][1] + b1;
            o0[px + 8] = acc[ni][2] + b0;
            o1[px + 8] = acc[ni][3] + b1;
        }
    }
}

// ---------------------------------------------------------------------------
// Kernel 4: fused bilinear gather (half2 lerp) + f16 mma (A single, B hi/lo).
// Block: 128 px x 64 oc, 256 threads / 8 warps. smem ~38.5 KB.
// ---------------------------------------------------------------------------
#define MPX_    128
#define ATILE_  (MPX_ * APITCH_)            // 9216 uint16
#define BTILE_  (C_ * APITCH_)              // 4608 uint16
#define SM_A    0
#define SM_BHI  (ATILE_ * 2)                // 18432
#define SM_BLO  (SM_BHI + BTILE_ * 2)       // 27648
#define SM_TIDX (SM_BLO + BTILE_ * 2)       // 36864
#define SM_TA   (SM_TIDX + MPX_ * 4)        // 37376
#define SM_TOT  (SM_TA + MPX_ * 8)          // 38400

struct __align__(8) TapA { float ax, ay; };

__global__ __launch_bounds__(256, 4) void fused_mma_kernel(float* __restrict__ out)
{
    extern __shared__ char sm[];
    uint16_t* Aa  = reinterpret_cast<uint16_t*>(sm + SM_A);
    uint16_t* Bhi = reinterpret_cast<uint16_t*>(sm + SM_BHI);
    uint16_t* Blo = reinterpret_cast<uint16_t*>(sm + SM_BLO);
    int*  tap_idx = reinterpret_cast<int*>(sm + SM_TIDX);
    TapA* tap_a   = reinterpret_cast<TapA*>(sm + SM_TA);

    const int tid  = threadIdx.x;
    const int wid  = tid >> 5;
    const int lane = tid & 31;
    const int b    = blockIdx.y;
    const int pix0 = blockIdx.x * MPX_;

    const int ocg = wid & 1;
    const int pxg = wid >> 1;

    float acc[2][4][4];
    #pragma unroll
    for (int mi = 0; mi < 2; ++mi)
        #pragma unroll
        for (int ni = 0; ni < 4; ++ni)
            #pragma unroll
            for (int r = 0; r < 4; ++r) acc[mi][ni][r] = 0.f;

    const __half* xb = g_xp + (size_t)b * HPWP_ * C_;
    const int cg = tid & 15;
    const int pb = tid >> 4;

    auto taps = [&](int kk) {
        if (tid < MPX_) {
            int pix = pix0 + tid;
            int oh = pix / W_, ow = pix % W_;
            float ox = g_off[((size_t)b * OC_ + kk) * HW_ + pix];
            float oy = g_off[((size_t)b * OC_ + KK_ + kk) * HW_ + pix];
            float cx = (float)(oh + kk / 3) + ox;
            float cy = (float)(ow + kk % 3) + oy;
            cx = fminf(fmaxf(cx, 0.f), (float)(HP_ - 1));
            cy = fminf(fmaxf(cy, 0.f), (float)(WP_ - 1));
            int tlx = (int)floorf(cx); tlx = min(max(tlx, 0), HP_ - 2);
            int tly = (int)floorf(cy); tly = min(max(tly, 0), WP_ - 2);
            tap_idx[tid] = tlx * WP_ + tly;
            tap_a[tid].ax = cx - (float)tlx;
            tap_a[tid].ay = cy - (float)tly;
        }
    };

    auto gather = [&]() {
        #pragma unroll 2
        for (int i = 0; i < 8; ++i) {
            int p = pb + 16 * i;
            int idx = tap_idx[p];
            TapA a = tap_a[p];
            __half2 ax2 = __float2half2_rn(a.ax);
            __half2 ay2 = __float2half2_rn(a.ay);
            const uint2* q = reinterpret_cast<const uint2*>(xb + (size_t)idx * C_) + cg;
            uint2 u00 = q[0];
            uint2 u01 = q[16];           // +1 col = +64 halfs
            uint2 u10 = q[WP_ * 16];     // +1 row
            uint2 u11 = q[(WP_ + 1) * 16];
            __half2 c00a = *reinterpret_cast<__half2*>(&u00.x);
            __half2 c00b = *reinterpret_cast<__half2*>(&u00.y);
            __half2 c01a = *reinterpret_cast<__half2*>(&u01.x);
            __half2 c01b = *reinterpret_cast<__half2*>(&u01.y);
            __half2 c10a = *reinterpret_cast<__half2*>(&u10.x);
            __half2 c10b = *reinterpret_cast<__half2*>(&u10.y);
            __half2 c11a = *reinterpret_cast<__half2*>(&u11.x);
            __half2 c11b = *reinterpret_cast<__half2*>(&u11.y);
            __half2 r0a = h2lerp(ay2, c00a, c01a);
            __half2 r1a = h2lerp(ay2, c10a, c11a);
            __half2 va  = h2lerp(ax2, r0a, r1a);
            __half2 r0b = h2lerp(ay2, c00b, c01b);
            __half2 r1b = h2lerp(ay2, c10b, c11b);
            __half2 vb  = h2lerp(ax2, r0b, r1b);
            uint2 o;
            memcpy(&o.x, &va, 4);
            memcpy(&o.y, &vb, 4);
            *reinterpret_cast<uint2*>(&Aa[p * APITCH_ + cg * 4]) = o;
        }
    };

    auto stageB = [&](int kk) {
        const uint2* sh = reinterpret_cast<const uint2*>(g_wtbh + kk * (C_*C_));
        const uint2* sl = reinterpret_cast<const uint2*>(g_wtbl + kk * (C_*C_));
        #pragma unroll
        for (int e = tid; e < 1024; e += 256) {
            int oc = e >> 4, c4 = e & 15;
            int doff = oc * APITCH_ + c4 * 4;
            *reinterpret_cast<uint2*>(&Bhi[doff]) = sh[e];
            *reinterpret_cast<uint2*>(&Blo[doff]) = sl[e];
        }
    };

    taps(0);
    __syncthreads();
    stageB(0);
    gather();
    __syncthreads();

    const int arow = pxg * 32 + (lane >> 2);
    const int akol = (lane & 3) * 2;
    const int brow = ocg * 32 + (lane >> 2);

    for (int kk = 0; kk < KK_; ++kk) {
        if (kk + 1 < KK_) taps(kk + 1);

        #pragma unroll
        for (int ki = 0; ki < 4; ++ki) {
            const int k0 = ki * 16 + akol;
            uint32_t a[2][4];
            #pragma unroll
            for (int mi = 0; mi < 2; ++mi) {
                int r0 = (arow + mi * 16) * APITCH_ + k0;
                int r1 = r0 + 8 * APITCH_;
                a[mi][0] = *reinterpret_cast<const uint32_t*>(&Aa[r0]);
                a[mi][1] = *reinterpret_cast<const uint32_t*>(&Aa[r1]);
                a[mi][2] = *reinterpret_cast<const uint32_t*>(&Aa[r0 + 8]);
                a[mi][3] = *reinterpret_cast<const uint32_t*>(&Aa[r1 + 8]);
            }
            #pragma unroll
            for (int ni = 0; ni < 4; ++ni) {
                int boff = (brow + ni * 8) * APITCH_ + k0;
                uint32_t bh0 = *reinterpret_cast<const uint32_t*>(&Bhi[boff]);
                uint32_t bh1 = *reinterpret_cast<const uint32_t*>(&Bhi[boff + 8]);
                uint32_t bl0 = *reinterpret_cast<const uint32_t*>(&Blo[boff]);
                uint32_t bl1 = *reinterpret_cast<const uint32_t*>(&Blo[boff + 8]);
                #pragma unroll
                for (int mi = 0; mi < 2; ++mi) {
                    float* d = acc[mi][ni];
                    mma16816(d[0], d[1], d[2], d[3],
                             a[mi][0], a[mi][1], a[mi][2], a[mi][3], bh0, bh1);
                    mma16816(d[0], d[1], d[2], d[3],
                             a[mi][0], a[mi][1], a[mi][2], a[mi][3], bl0, bl1);
                }
            }
        }
        if (kk + 1 < KK_) {
            __syncthreads();
            stageB(kk + 1);
            gather();
            __syncthreads();
        }
    }

    #pragma unroll
    for (int mi = 0; mi < 2; ++mi) {
        int px = pix0 + pxg * 32 + mi * 16 + (lane >> 2);
        #pragma unroll
        for (int ni = 0; ni < 4; ++ni) {
            int oc = ocg * 32 + ni * 8 + (lane & 3) * 2;
            float* o0 = out + ((size_t)b * C_ + oc) * HW_;
            float* o1 = out + ((size_t)b * C_ + oc + 1) * HW_;
            o0[px]     = acc[mi][ni][0];
            o1[px]     = acc[mi][ni][1];
            o0[px + 8] = acc[mi][ni][2];
            o1[px + 8] = acc[mi][ni][3];
        }
    }
}

// ---------------------------------------------------------------------------
// Launch
// ---------------------------------------------------------------------------
extern "C" void kernel_launch(void* const* d_in, const int* in_sizes, int n_in,
                              void* d_out, int out_size) {
    const float* x      = (const float*)d_in[0];
    const float* depth  = (const float*)d_in[1];
    const float* w_off  = (const float*)d_in[2];
    const float* bias   = (const float*)d_in[3];
    const float* weight = (const float*)d_in[4];
    float* out = (float*)d_out;

    {
        dim3 grid(295, 4);   // 295*256 = 75520 >= all job sizes
        prep_kernel<<<grid, 256>>>(weight, w_off, depth);
    }
    {
        dim3 grid(HW_ / 32, B_);
        nhwc_kernel<<<grid, 256>>>(x);
    }
    {
        dim3 grid(HW_ / 128, B_);
        offmma_kernel<<<grid, 256>>>(bias);
    }
    {
        static bool attr_set = false;
        if (!attr_set) {
            cudaFuncSetAttribute(fused_mma_kernel,
                                 cudaFuncAttributeMaxDynamicSharedMemorySize, SM_TOT);
            attr_set = true;
        }
        dim3 grid(HW_ / MPX_, B_);
        fused_mma_kernel<<<grid, 256, SM_TOT>>>(out);
    }
}